// round 1
// baseline (speedup 1.0000x reference)
#include <cuda_runtime.h>
#include <cstdint>
#include <cstddef>

// ---------------------------------------------------------------------------
// Scratch (single __device__ array; no allocations anywhere)
// ---------------------------------------------------------------------------
static constexpr size_t S_B1  = 64ull * 96 * 4092;
static constexpr size_t S_B2  = 64ull * 96 * 2044;
static constexpr size_t S_B3  = 64ull * 96 * 1020;
static constexpr size_t S_B4  = 64ull * 96 * 508;
static constexpr size_t S_B4P = 64ull * 96 * 254;
static constexpr size_t S_B5  = 64ull * 96 * 125;
static constexpr size_t S_B5P = 64ull * 96 * 62;
static constexpr size_t S_B6  = 64ull * 96 * 29;
static constexpr size_t S_B7  = 64ull * 128 * 14;
static constexpr size_t S_WT1 = 40ull * 10 * 96;
static constexpr size_t S_WT2 = 96ull * 5 * 96;   // same for wt3..wt6
static constexpr size_t S_WT7 = 96ull * 3 * 128;

static constexpr size_t OFF_B1  = 0;
static constexpr size_t OFF_B2  = OFF_B1  + S_B1;
static constexpr size_t OFF_B3  = OFF_B2  + S_B2;
static constexpr size_t OFF_B4  = OFF_B3  + S_B3;
static constexpr size_t OFF_B4P = OFF_B4  + S_B4;
static constexpr size_t OFF_B5  = OFF_B4P + S_B4P;
static constexpr size_t OFF_B5P = OFF_B5  + S_B5;
static constexpr size_t OFF_B6  = OFF_B5P + S_B5P;
static constexpr size_t OFF_B7  = OFF_B6  + S_B6;
static constexpr size_t OFF_WT1 = OFF_B7  + S_B7;
static constexpr size_t OFF_WT2 = OFF_WT1 + S_WT1;
static constexpr size_t OFF_WT3 = OFF_WT2 + S_WT2;
static constexpr size_t OFF_WT4 = OFF_WT3 + S_WT2;
static constexpr size_t OFF_WT5 = OFF_WT4 + S_WT2;
static constexpr size_t OFF_WT6 = OFF_WT5 + S_WT2;
static constexpr size_t OFF_WT7 = OFF_WT6 + S_WT2;
static constexpr size_t SCRATCH_TOTAL = OFF_WT7 + S_WT7;

__device__ float g_scratch[SCRATCH_TOTAL];

// ---------------------------------------------------------------------------
// f32x2 packed-FMA helpers (Blackwell double-rate fp32 path)
// ---------------------------------------------------------------------------
__device__ __forceinline__ unsigned long long pk2(float lo, float hi) {
    unsigned long long r;
    asm("mov.b64 %0, {%1, %2};" : "=l"(r)
        : "r"(__float_as_uint(lo)), "r"(__float_as_uint(hi)));
    return r;
}
__device__ __forceinline__ void fma2(unsigned long long& d,
                                     unsigned long long a,
                                     unsigned long long b) {
    asm("fma.rn.f32x2 %0, %1, %2, %0;" : "+l"(d) : "l"(a), "l"(b));
}
__device__ __forceinline__ float2 unpk2(unsigned long long v) {
    unsigned int a, b;
    asm("mov.b64 {%0, %1}, %2;" : "=r"(a), "=r"(b) : "l"(v));
    return make_float2(__uint_as_float(a), __uint_as_float(b));
}

// ---------------------------------------------------------------------------
// Weight transpose: w[O][I][K] (torch layout) -> wt[(i*K + k)*O + o]
// Coalesced read, scattered write; tiny and runs once per graph replay.
// ---------------------------------------------------------------------------
__global__ void transpose_w_kernel(const float* __restrict__ w,
                                   float* __restrict__ wt,
                                   int O, int I, int K) {
    int n = blockIdx.x * blockDim.x + threadIdx.x;
    int total = O * I * K;
    if (n >= total) return;
    int o = n / (I * K);
    int r = n - o * (I * K);
    int i = r / K;
    int k = r - i * K;
    wt[(i * K + k) * O + o] = w[n];
}

// ---------------------------------------------------------------------------
// Direct stride-2 VALID conv, fp32 via packed f32x2.
//   x : [B][I][Tin]     wt : [(i*K+k)*O + o]      y : [B][O][Tconv]
// Block: (T_TILE conv outputs) x (all O channels) for one batch sample.
// 256 threads = 32 time-lanes x 8 channel-groups. Each thread: CO channels,
// TO = T_TILE/32 positions (paired into f32x2 accumulators).
// Shared input is de-interleaved even/odd so stride-2 reads are lane-stride-1
// (conflict-free). Weight reads are warp-uniform LDS.128 broadcasts.
// ---------------------------------------------------------------------------
template <int I, int O, int K, int ICHUNK, int T_TILE, bool RELU>
__global__ __launch_bounds__(256, 1)
void conv_kernel(const float* __restrict__ x, const float* __restrict__ wt,
                 const float* __restrict__ bias, float* __restrict__ y,
                 int Tin, int Tconv) {
    constexpr int SPAN_H = T_TILE + 16;     // half-span (even/odd arrays)
    constexpr int TO = T_TILE / 32;
    constexpr int NP = TO / 2;              // f32x2 position pairs
    constexpr int CO = O / 8;
    static_assert(CO % 4 == 0, "CO must be multiple of 4 for float4 weights");

    extern __shared__ float smem[];
    float* xe  = smem;                       // [I][SPAN_H] even phase
    float* xo  = xe + I * SPAN_H;            // [I][SPAN_H] odd phase
    float* wsh = xo + I * SPAN_H;            // [ICHUNK*K*O]
    float* bsh = wsh + ICHUNK * K * O;       // [O]

    const int b   = blockIdx.y;
    const int t0  = blockIdx.x * T_TILE;
    const int tid = threadIdx.x;
    const int tx  = tid & 31;
    const int cy  = tid >> 5;

    if (tid < O) bsh[tid] = bias[tid];

    // Load + de-interleave input tile. x[b][i][2*t0 + j], j in [0, JSPAN)
    const int JSPAN = 2 * T_TILE + K;
    const float* xb = x + ((size_t)b * I) * Tin + 2 * t0;
    for (int i = 0; i < I; i++) {
        float* de = xe + i * SPAN_H;
        float* dd = xo + i * SPAN_H;
        const float* src = xb + (size_t)i * Tin;
        for (int j = tid; j < JSPAN; j += 256) {
            float v = (2 * t0 + j < Tin) ? src[j] : 0.f;
            if (j & 1) dd[j >> 1] = v;
            else       de[j >> 1] = v;
        }
    }
    __syncthreads();

    unsigned long long acc[CO][NP];
#pragma unroll
    for (int c = 0; c < CO; c++) {
        float bv = bsh[cy * CO + c];
        unsigned long long bp = pk2(bv, bv);
#pragma unroll
        for (int j = 0; j < NP; j++) acc[c][j] = bp;
    }

    for (int ic0 = 0; ic0 < I; ic0 += ICHUNK) {
        __syncthreads();
        const float* wsrc = wt + (size_t)ic0 * K * O;
        for (int n = tid; n < ICHUNK * K * O; n += 256) wsh[n] = wsrc[n];
        __syncthreads();

        for (int ic = 0; ic < ICHUNK; ic++) {
            const float* xer = xe + (ic0 + ic) * SPAN_H + tx;
            const float* xod = xo + (ic0 + ic) * SPAN_H + tx;
            const float* wrow = wsh + (ic * K) * O + cy * CO;
#pragma unroll
            for (int k = 0; k < K; k++) {
                const float* xs = (k & 1) ? xod : xer;
                const int h = k >> 1;
                unsigned long long xp[NP];
#pragma unroll
                for (int j = 0; j < NP; j++)
                    xp[j] = pk2(xs[h + 64 * j], xs[h + 64 * j + 32]);
                const float4* wq =
                    reinterpret_cast<const float4*>(wrow + k * O);
#pragma unroll
                for (int c4 = 0; c4 < CO / 4; c4++) {
                    float4 wv = wq[c4];
                    unsigned long long wp0 = pk2(wv.x, wv.x);
                    unsigned long long wp1 = pk2(wv.y, wv.y);
                    unsigned long long wp2 = pk2(wv.z, wv.z);
                    unsigned long long wp3 = pk2(wv.w, wv.w);
#pragma unroll
                    for (int j = 0; j < NP; j++) {
                        fma2(acc[c4 * 4 + 0][j], wp0, xp[j]);
                        fma2(acc[c4 * 4 + 1][j], wp1, xp[j]);
                        fma2(acc[c4 * 4 + 2][j], wp2, xp[j]);
                        fma2(acc[c4 * 4 + 3][j], wp3, xp[j]);
                    }
                }
            }
        }
    }

    // Store (coalesced across the 32 time-lanes per (o, pair-half))
#pragma unroll
    for (int c = 0; c < CO; c++) {
        const int o = cy * CO + c;
        float* yr = y + ((size_t)b * O + o) * Tconv;
#pragma unroll
        for (int j = 0; j < NP; j++) {
            float2 v = unpk2(acc[c][j]);
            float v0 = RELU ? fmaxf(v.x, 0.f) : v.x;
            float v1 = RELU ? fmaxf(v.y, 0.f) : v.y;
            int tA = t0 + tx + 64 * j;
            int tB = tA + 32;
            if (tA < Tconv) yr[tA] = v0;
            if (tB < Tconv) yr[tB] = v1;
        }
    }
}

// ---------------------------------------------------------------------------
// AvgPool1d(k=2,s=2) + ReLU
// ---------------------------------------------------------------------------
__global__ void pool_relu_kernel(const float* __restrict__ in,
                                 float* __restrict__ out,
                                 int Tc, int total) {
    int n = blockIdx.x * blockDim.x + threadIdx.x;
    if (n >= total) return;
    int To = Tc >> 1;
    int row = n / To;
    int u = n - row * To;
    const float* r = in + (size_t)row * Tc + 2 * u;
    float v = 0.5f * (r[0] + r[1]);
    out[n] = fmaxf(v, 0.f);
}

// ---------------------------------------------------------------------------
// Masked adaptive-max over valid frames + 3-layer MLP head
// ---------------------------------------------------------------------------
__global__ void head_kernel(const float* __restrict__ y7,       // [64][128][14]
                            const int* __restrict__ len_mask,
                            const float* __restrict__ lw1, const float* __restrict__ lb1,
                            const float* __restrict__ lw2, const float* __restrict__ lb2,
                            const float* __restrict__ lw3, const float* __restrict__ lb3,
                            float* __restrict__ out) {
    __shared__ float v[128], h1[128], h2[64];
    const int b = blockIdx.x;
    const int tid = threadIdx.x;

    int L = len_mask[b];
    L = (L - 10) / 2 + 1;   // conv1
    L = (L - 5) / 2 + 1;    // conv2
    L = (L - 5) / 2 + 1;    // conv3
    L = (L - 5) / 2 + 1;    // conv4
    L >>= 1;                // pool
    L = (L - 5) / 2 + 1;    // conv5
    L >>= 1;                // pool
    L = (L - 5) / 2 + 1;    // conv6
    L = (L - 3) / 2 + 1;    // conv7
    if (L > 14) L = 14;
    if (L < 1)  L = 1;

    const float* row = y7 + ((size_t)b * 128 + tid) * 14;
    float m = -3.4e38f;
    for (int t = 0; t < L; t++) m = fmaxf(m, row[t]);
    v[tid] = m;
    __syncthreads();

    float s = lb1[tid];
#pragma unroll 8
    for (int i = 0; i < 128; i++) s += lw1[tid * 128 + i] * v[i];
    h1[tid] = fmaxf(s, 0.f);
    __syncthreads();

    if (tid < 64) {
        float s2 = lb2[tid];
#pragma unroll 8
        for (int i = 0; i < 128; i++) s2 += lw2[tid * 128 + i] * h1[i];
        h2[tid] = fmaxf(s2, 0.f);
    }
    __syncthreads();

    if (tid < 5) {
        float s3 = lb3[tid];
#pragma unroll 8
        for (int i = 0; i < 64; i++) s3 += lw3[tid * 64 + i] * h2[i];
        out[b * 5 + tid] = s3;
    }
}

// ---------------------------------------------------------------------------
// Launch
// ---------------------------------------------------------------------------
extern "C" void kernel_launch(void* const* d_in, const int* in_sizes, int n_in,
                              void* d_out, int out_size) {
    const float* x    = (const float*)d_in[0];
    const int*   lenm = (const int*)d_in[1];
    const float* w1 = (const float*)d_in[2];  const float* b1 = (const float*)d_in[3];
    const float* w2 = (const float*)d_in[4];  const float* b2 = (const float*)d_in[5];
    const float* w3 = (const float*)d_in[6];  const float* b3 = (const float*)d_in[7];
    const float* w4 = (const float*)d_in[8];  const float* b4 = (const float*)d_in[9];
    const float* w5 = (const float*)d_in[10]; const float* b5 = (const float*)d_in[11];
    const float* w6 = (const float*)d_in[12]; const float* b6 = (const float*)d_in[13];
    const float* w7 = (const float*)d_in[14]; const float* b7 = (const float*)d_in[15];
    const float* lw1 = (const float*)d_in[16]; const float* lb1 = (const float*)d_in[17];
    const float* lw2 = (const float*)d_in[18]; const float* lb2 = (const float*)d_in[19];
    const float* lw3 = (const float*)d_in[20]; const float* lb3 = (const float*)d_in[21];

    float* base = nullptr;
    cudaGetSymbolAddress((void**)&base, g_scratch);
    float* B1  = base + OFF_B1;
    float* B2  = base + OFF_B2;
    float* B3  = base + OFF_B3;
    float* B4  = base + OFF_B4;
    float* B4P = base + OFF_B4P;
    float* B5  = base + OFF_B5;
    float* B5P = base + OFF_B5P;
    float* B6  = base + OFF_B6;
    float* B7  = base + OFF_B7;
    float* WT1 = base + OFF_WT1;
    float* WT2 = base + OFF_WT2;
    float* WT3 = base + OFF_WT3;
    float* WT4 = base + OFF_WT4;
    float* WT5 = base + OFF_WT5;
    float* WT6 = base + OFF_WT6;
    float* WT7 = base + OFF_WT7;

    // dynamic smem sizes (bytes)
    const int SM1   = (2 * 40 * 144 + 40 * 10 * 96 + 96) * 4;   // 200064
    const int SM2   = (2 * 96 * 144 + 32 * 5 * 96 + 96) * 4;    // 172416
    const int SM2_64= (2 * 96 * 80  + 32 * 5 * 96 + 96) * 4;    // 123264
    const int SM7_64= (2 * 96 * 80  + 32 * 3 * 128 + 128) * 4;  // 111104

    cudaFuncSetAttribute(conv_kernel<40, 96, 10, 40, 128, true>,
                         cudaFuncAttributeMaxDynamicSharedMemorySize, SM1);
    cudaFuncSetAttribute(conv_kernel<96, 96, 5, 32, 128, true>,
                         cudaFuncAttributeMaxDynamicSharedMemorySize, SM2);
    cudaFuncSetAttribute(conv_kernel<96, 96, 5, 32, 128, false>,
                         cudaFuncAttributeMaxDynamicSharedMemorySize, SM2);
    cudaFuncSetAttribute(conv_kernel<96, 96, 5, 32, 64, false>,
                         cudaFuncAttributeMaxDynamicSharedMemorySize, SM2_64);
    cudaFuncSetAttribute(conv_kernel<96, 96, 5, 32, 64, true>,
                         cudaFuncAttributeMaxDynamicSharedMemorySize, SM2_64);
    cudaFuncSetAttribute(conv_kernel<96, 128, 3, 32, 64, true>,
                         cudaFuncAttributeMaxDynamicSharedMemorySize, SM7_64);

    // Weight transposes (run every replay; deterministic, ~µs)
    transpose_w_kernel<<<(96 * 40 * 10 + 255) / 256, 256>>>(w1, WT1, 96, 40, 10);
    transpose_w_kernel<<<(96 * 96 * 5 + 255) / 256, 256>>>(w2, WT2, 96, 96, 5);
    transpose_w_kernel<<<(96 * 96 * 5 + 255) / 256, 256>>>(w3, WT3, 96, 96, 5);
    transpose_w_kernel<<<(96 * 96 * 5 + 255) / 256, 256>>>(w4, WT4, 96, 96, 5);
    transpose_w_kernel<<<(96 * 96 * 5 + 255) / 256, 256>>>(w5, WT5, 96, 96, 5);
    transpose_w_kernel<<<(96 * 96 * 5 + 255) / 256, 256>>>(w6, WT6, 96, 96, 5);
    transpose_w_kernel<<<(128 * 96 * 3 + 255) / 256, 256>>>(w7, WT7, 128, 96, 3);

    // Conv stack
    conv_kernel<40, 96, 10, 40, 128, true><<<dim3(32, 64), 256, SM1>>>(
        x, WT1, b1, B1, 8192, 4092);
    conv_kernel<96, 96, 5, 32, 128, true><<<dim3(16, 64), 256, SM2>>>(
        B1, WT2, b2, B2, 4092, 2044);
    conv_kernel<96, 96, 5, 32, 128, true><<<dim3(8, 64), 256, SM2>>>(
        B2, WT3, b3, B3, 2044, 1020);
    conv_kernel<96, 96, 5, 32, 128, false><<<dim3(4, 64), 256, SM2>>>(
        B3, WT4, b4, B4, 1020, 508);
    pool_relu_kernel<<<(64 * 96 * 254 + 255) / 256, 256>>>(B4, B4P, 508, 64 * 96 * 254);
    conv_kernel<96, 96, 5, 32, 64, false><<<dim3(2, 64), 256, SM2_64>>>(
        B4P, WT5, b5, B5, 254, 125);
    pool_relu_kernel<<<(64 * 96 * 62 + 255) / 256, 256>>>(B5, B5P, 125, 64 * 96 * 62);
    conv_kernel<96, 96, 5, 32, 64, true><<<dim3(1, 64), 256, SM2_64>>>(
        B5P, WT6, b6, B6, 62, 29);
    conv_kernel<96, 128, 3, 32, 64, true><<<dim3(1, 64), 256, SM7_64>>>(
        B6, WT7, b7, B7, 29, 14);

    // Masked max + MLP head
    head_kernel<<<64, 128>>>(B7, lenm, lw1, lb1, lw2, lb2, lw3, lb3,
                             (float*)d_out);
}

// round 2
// speedup vs baseline: 1.9537x; 1.9537x over previous
#include <cuda_runtime.h>
#include <cstdint>
#include <cstddef>

typedef unsigned long long u64;

// ---------------------------------------------------------------------------
// Scratch (single __device__ array; no allocations anywhere)
// ---------------------------------------------------------------------------
static constexpr size_t S_B1  = 64ull * 96 * 4092;
static constexpr size_t S_B2  = 64ull * 96 * 2044;
static constexpr size_t S_B3  = 64ull * 96 * 1020;
static constexpr size_t S_B4  = 64ull * 96 * 508;
static constexpr size_t S_B5  = 64ull * 96 * 125;
static constexpr size_t S_B6  = 64ull * 96 * 29;
static constexpr size_t S_B7  = 64ull * 128 * 14;
static constexpr size_t S_WT1 = 40ull * 10 * 96;    // 38400
static constexpr size_t S_WT2 = 96ull * 5 * 96;     // 46080 (wt2..wt6)
static constexpr size_t S_WT7 = 96ull * 3 * 128;    // 36864

static constexpr size_t OFF_B1  = 0;
static constexpr size_t OFF_B2  = OFF_B1  + S_B1;
static constexpr size_t OFF_B3  = OFF_B2  + S_B2;
static constexpr size_t OFF_B4  = OFF_B3  + S_B3;
static constexpr size_t OFF_B5  = OFF_B4  + S_B4;
static constexpr size_t OFF_B6  = OFF_B5  + S_B5;
static constexpr size_t OFF_B7  = OFF_B6  + S_B6;
static constexpr size_t OFF_WT1 = OFF_B7  + S_B7;
static constexpr size_t OFF_WT2 = OFF_WT1 + S_WT1;
static constexpr size_t OFF_WT3 = OFF_WT2 + S_WT2;
static constexpr size_t OFF_WT4 = OFF_WT3 + S_WT2;
static constexpr size_t OFF_WT5 = OFF_WT4 + S_WT2;
static constexpr size_t OFF_WT6 = OFF_WT5 + S_WT2;
static constexpr size_t OFF_WT7 = OFF_WT6 + S_WT2;
static constexpr size_t SCRATCH_TOTAL = OFF_WT7 + S_WT7;

__device__ float g_scratch[SCRATCH_TOTAL];

// ---------------------------------------------------------------------------
// f32x2 packed-FMA helpers
// ---------------------------------------------------------------------------
__device__ __forceinline__ u64 pk2(float lo, float hi) {
    u64 r;
    asm("mov.b64 %0, {%1, %2};" : "=l"(r)
        : "r"(__float_as_uint(lo)), "r"(__float_as_uint(hi)));
    return r;
}
__device__ __forceinline__ void fma2(u64& d, u64 a, u64 b) {
    asm("fma.rn.f32x2 %0, %1, %2, %0;" : "+l"(d) : "l"(a), "l"(b));
}
__device__ __forceinline__ float2 unpk2(u64 v) {
    unsigned int a, b;
    asm("mov.b64 {%0, %1}, %2;" : "=r"(a), "=r"(b) : "l"(v));
    return make_float2(__uint_as_float(a), __uint_as_float(b));
}

// ---------------------------------------------------------------------------
// Fused weight transpose: w[O][I][K] -> wt[(i*K+k)*O + o], all 7 tensors in
// one launch (keeps launch #5 = a conv1 slice for ncu -s 5 -c 1).
// ---------------------------------------------------------------------------
__device__ __forceinline__ void tp_one(const float* __restrict__ w,
                                       float* __restrict__ wt,
                                       int O, int I, int K, int n) {
    int IK = I * K;
    int o = n / IK;
    int r = n - o * IK;
    int i = r / K;
    int k = r - i * K;
    wt[(i * K + k) * O + o] = w[n];
}

__global__ void transpose_all_kernel(
    const float* __restrict__ w1, const float* __restrict__ w2,
    const float* __restrict__ w3, const float* __restrict__ w4,
    const float* __restrict__ w5, const float* __restrict__ w6,
    const float* __restrict__ w7,
    float* __restrict__ t1, float* __restrict__ t2, float* __restrict__ t3,
    float* __restrict__ t4, float* __restrict__ t5, float* __restrict__ t6,
    float* __restrict__ t7) {
    int n = blockIdx.x * blockDim.x + threadIdx.x;
    if (n < 38400) { tp_one(w1, t1, 96, 40, 10, n); return; }  n -= 38400;
    if (n < 46080) { tp_one(w2, t2, 96, 96, 5, n); return; }   n -= 46080;
    if (n < 46080) { tp_one(w3, t3, 96, 96, 5, n); return; }   n -= 46080;
    if (n < 46080) { tp_one(w4, t4, 96, 96, 5, n); return; }   n -= 46080;
    if (n < 46080) { tp_one(w5, t5, 96, 96, 5, n); return; }   n -= 46080;
    if (n < 46080) { tp_one(w6, t6, 96, 96, 5, n); return; }   n -= 46080;
    if (n < 36864) { tp_one(w7, t7, 128, 96, 3, n); }
}

// ---------------------------------------------------------------------------
// Direct stride-2 VALID conv, fp32 via packed f32x2, CHANNEL-paired:
//   acc pair = (out_ch o, o+1); weight pair loaded as one LDS.64 (no movs),
//   x duplicated into both halves (1 mov per time-reg).
//   x : [B][I][TinRaw]   wt : [(i*K+k)*O + o]   y : [B][O][Tconv]
// Optional POOL_IN: input element t = relu(0.5*(raw[2t] + raw[2t+1]))
// computed during smem staging (fuses AvgPool1d(2)+ReLU of previous layer).
// Shared input de-interleaved even/odd so stride-2 taps are lane-stride-1.
// 256 threads = 32 time-lanes x 8 channel-groups; 2 CTAs/SM for latency hiding.
// ---------------------------------------------------------------------------
template <int I, int O, int K, int ICHUNK, int T_TILE, bool RELU, bool POOL_IN>
__global__ __launch_bounds__(256, 2)
void conv_kernel(const float* __restrict__ x, const float* __restrict__ wt,
                 const float* __restrict__ bias, float* __restrict__ y,
                 int Tin, int TinRaw, int Tconv) {
    constexpr int SPAN_H = T_TILE + 8;      // half-span (even/odd arrays)
    constexpr int TO = T_TILE / 32;         // time regs per thread
    constexpr int CO = O / 8;               // channels per thread
    constexpr int CP = CO / 2;              // channel pairs (f32x2)
    constexpr int USPAN = 2 * T_TILE + K + 1;
    static_assert((USPAN + 1) / 2 <= SPAN_H, "span");

    extern __shared__ float smem[];
    float* xe  = smem;                      // [I][SPAN_H] even phase
    float* xo  = xe + I * SPAN_H;           // [I][SPAN_H] odd phase
    float* wsh = xo + I * SPAN_H;           // [ICHUNK*K*O]

    const int b   = blockIdx.y;
    const int t0  = blockIdx.x * T_TILE;
    const int tid = threadIdx.x;
    const int tx  = tid & 31;
    const int cy  = tid >> 5;

    // Stage (and optionally pool+relu) input tile
    const float* xb = x + (size_t)b * I * TinRaw;
    for (int n = tid; n < I * USPAN; n += 256) {
        int i = n / USPAN;
        int u = n - i * USPAN;
        int tg = 2 * t0 + u;                // logical input position
        float v = 0.f;
        if (tg < Tin) {
            if (POOL_IN) {
                const float* s = xb + (size_t)i * TinRaw + 2 * tg;
                v = fmaxf(0.5f * (s[0] + s[1]), 0.f);
            } else {
                v = xb[(size_t)i * TinRaw + tg];
            }
        }
        if (u & 1) xo[i * SPAN_H + (u >> 1)] = v;
        else       xe[i * SPAN_H + (u >> 1)] = v;
    }

    // Init accumulators with bias pairs (direct 64-bit gmem load = packed)
    u64 acc[CP][TO];
    const u64* bp64 = reinterpret_cast<const u64*>(bias) + (size_t)cy * CP;
#pragma unroll
    for (int p = 0; p < CP; p++) {
        u64 bb = bp64[p];
#pragma unroll
        for (int j = 0; j < TO; j++) acc[p][j] = bb;
    }

    for (int ic0 = 0; ic0 < I; ic0 += ICHUNK) {
        __syncthreads();
        {
            const float4* wsrc =
                reinterpret_cast<const float4*>(wt + (size_t)ic0 * K * O);
            float4* wdst = reinterpret_cast<float4*>(wsh);
            constexpr int W4 = ICHUNK * K * O / 4;
            for (int n = tid; n < W4; n += 256) wdst[n] = wsrc[n];
        }
        __syncthreads();

        for (int ic = 0; ic < ICHUNK; ic++) {
            const float* xer = xe + (ic0 + ic) * SPAN_H + tx;
            const float* xod = xo + (ic0 + ic) * SPAN_H + tx;
#pragma unroll
            for (int k = 0; k < K; k++) {
                const float* xs = (k & 1) ? xod : xer;
                const int h = k >> 1;
                u64 xp[TO];
#pragma unroll
                for (int j = 0; j < TO; j++) {
                    float xv = xs[h + 32 * j];
                    xp[j] = pk2(xv, xv);
                }
                const u64* w64 =
                    reinterpret_cast<const u64*>(wsh + (ic * K + k) * O) +
                    cy * CP;
#pragma unroll
                for (int p = 0; p < CP; p++) {
                    u64 wp = w64[p];        // (w[o], w[o+1]) packed, LDS.64
#pragma unroll
                    for (int j = 0; j < TO; j++) fma2(acc[p][j], wp, xp[j]);
                }
            }
        }
    }

    // Store: lanes write consecutive t per channel row (coalesced)
#pragma unroll
    for (int p = 0; p < CP; p++) {
        const int o0 = cy * CO + 2 * p;
        float* y0 = y + ((size_t)b * O + o0) * Tconv;
        float* y1 = y0 + Tconv;
#pragma unroll
        for (int j = 0; j < TO; j++) {
            float2 v = unpk2(acc[p][j]);
            if (RELU) { v.x = fmaxf(v.x, 0.f); v.y = fmaxf(v.y, 0.f); }
            int t = t0 + tx + 32 * j;
            if (t < Tconv) { y0[t] = v.x; y1[t] = v.y; }
        }
    }
}

// ---------------------------------------------------------------------------
// Masked adaptive-max over valid frames + 3-layer MLP head
// ---------------------------------------------------------------------------
__global__ void head_kernel(const float* __restrict__ y7,       // [64][128][14]
                            const int* __restrict__ len_mask,
                            const float* __restrict__ lw1, const float* __restrict__ lb1,
                            const float* __restrict__ lw2, const float* __restrict__ lb2,
                            const float* __restrict__ lw3, const float* __restrict__ lb3,
                            float* __restrict__ out) {
    __shared__ float v[128], h1[128], h2[64];
    const int b = blockIdx.x;
    const int tid = threadIdx.x;

    int L = len_mask[b];
    L = (L - 10) / 2 + 1;   // conv1
    L = (L - 5) / 2 + 1;    // conv2
    L = (L - 5) / 2 + 1;    // conv3
    L = (L - 5) / 2 + 1;    // conv4
    L >>= 1;                // pool
    L = (L - 5) / 2 + 1;    // conv5
    L >>= 1;                // pool
    L = (L - 5) / 2 + 1;    // conv6
    L = (L - 3) / 2 + 1;    // conv7
    if (L > 14) L = 14;
    if (L < 1)  L = 1;

    const float* row = y7 + ((size_t)b * 128 + tid) * 14;
    float m = -3.4e38f;
    for (int t = 0; t < L; t++) m = fmaxf(m, row[t]);
    v[tid] = m;
    __syncthreads();

    float s = lb1[tid];
#pragma unroll 8
    for (int i = 0; i < 128; i++) s += lw1[tid * 128 + i] * v[i];
    h1[tid] = fmaxf(s, 0.f);
    __syncthreads();

    if (tid < 64) {
        float s2 = lb2[tid];
#pragma unroll 8
        for (int i = 0; i < 128; i++) s2 += lw2[tid * 128 + i] * h1[i];
        h2[tid] = fmaxf(s2, 0.f);
    }
    __syncthreads();

    if (tid < 5) {
        float s3 = lb3[tid];
#pragma unroll 8
        for (int i = 0; i < 64; i++) s3 += lw3[tid * 64 + i] * h2[i];
        out[b * 5 + tid] = s3;
    }
}

// ---------------------------------------------------------------------------
// Launch
// ---------------------------------------------------------------------------
extern "C" void kernel_launch(void* const* d_in, const int* in_sizes, int n_in,
                              void* d_out, int out_size) {
    const float* x    = (const float*)d_in[0];
    const int*   lenm = (const int*)d_in[1];
    const float* w1 = (const float*)d_in[2];  const float* b1 = (const float*)d_in[3];
    const float* w2 = (const float*)d_in[4];  const float* b2 = (const float*)d_in[5];
    const float* w3 = (const float*)d_in[6];  const float* b3 = (const float*)d_in[7];
    const float* w4 = (const float*)d_in[8];  const float* b4 = (const float*)d_in[9];
    const float* w5 = (const float*)d_in[10]; const float* b5 = (const float*)d_in[11];
    const float* w6 = (const float*)d_in[12]; const float* b6 = (const float*)d_in[13];
    const float* w7 = (const float*)d_in[14]; const float* b7 = (const float*)d_in[15];
    const float* lw1 = (const float*)d_in[16]; const float* lb1 = (const float*)d_in[17];
    const float* lw2 = (const float*)d_in[18]; const float* lb2 = (const float*)d_in[19];
    const float* lw3 = (const float*)d_in[20]; const float* lb3 = (const float*)d_in[21];

    float* base = nullptr;
    cudaGetSymbolAddress((void**)&base, g_scratch);
    float* B1  = base + OFF_B1;
    float* B2  = base + OFF_B2;
    float* B3  = base + OFF_B3;
    float* B4  = base + OFF_B4;
    float* B5  = base + OFF_B5;
    float* B6  = base + OFF_B6;
    float* B7  = base + OFF_B7;
    float* WT1 = base + OFF_WT1;
    float* WT2 = base + OFF_WT2;
    float* WT3 = base + OFF_WT3;
    float* WT4 = base + OFF_WT4;
    float* WT5 = base + OFF_WT5;
    float* WT6 = base + OFF_WT6;
    float* WT7 = base + OFF_WT7;

    // Template instantiations + dynamic smem (bytes)
    auto k1 = conv_kernel<40, 96, 10, 10, 128, true,  false>;
    auto k2 = conv_kernel<96, 96, 5,  16, 96,  true,  false>;
    auto k4 = conv_kernel<96, 96, 5,  16, 96,  false, false>;
    auto k5 = conv_kernel<96, 96, 5,  16, 64,  false, true>;
    auto k6 = conv_kernel<96, 96, 5,  16, 32,  true,  true>;
    auto k7 = conv_kernel<96, 128, 3, 32, 32,  true,  false>;

    const int SM1 = (2 * 40 * 136 + 10 * 10 * 96) * 4;   // 81920
    const int SM2 = (2 * 96 * 104 + 16 * 5 * 96) * 4;    // 110592
    const int SM5 = (2 * 96 * 72  + 16 * 5 * 96) * 4;    // 86016
    const int SM6 = (2 * 96 * 40  + 16 * 5 * 96) * 4;    // 61440
    const int SM7 = (2 * 96 * 40  + 32 * 3 * 128) * 4;   // 79872

    cudaFuncSetAttribute(k1, cudaFuncAttributeMaxDynamicSharedMemorySize, SM1);
    cudaFuncSetAttribute(k2, cudaFuncAttributeMaxDynamicSharedMemorySize, SM2);
    cudaFuncSetAttribute(k4, cudaFuncAttributeMaxDynamicSharedMemorySize, SM2);
    cudaFuncSetAttribute(k5, cudaFuncAttributeMaxDynamicSharedMemorySize, SM5);
    cudaFuncSetAttribute(k6, cudaFuncAttributeMaxDynamicSharedMemorySize, SM6);
    cudaFuncSetAttribute(k7, cudaFuncAttributeMaxDynamicSharedMemorySize, SM7);

    // Launch 0: all weight transposes fused
    transpose_all_kernel<<<(38400 + 5 * 46080 + 36864 + 255) / 256, 256>>>(
        w1, w2, w3, w4, w5, w6, w7, WT1, WT2, WT3, WT4, WT5, WT6, WT7);

    // Launches 1-5: conv1 split over batch so ncu (-s 5 -c 1) captures a slice
    {
        const int nT = (4092 + 127) / 128;  // 32
        int b0 = 0;
        const int chunks[5] = {13, 13, 13, 13, 12};
        for (int c = 0; c < 5; c++) {
            int nb = chunks[c];
            k1<<<dim3(nT, nb), 256, SM1>>>(
                x + (size_t)b0 * 40 * 8192, WT1, b1,
                B1 + (size_t)b0 * 96 * 4092, 8192, 8192, 4092);
            b0 += nb;
        }
    }

    // conv2..conv4 (pool of conv4 fused into conv5's staging)
    k2<<<dim3((2044 + 95) / 96, 64), 256, SM2>>>(B1, WT2, b2, B2, 4092, 4092, 2044);
    k2<<<dim3((1020 + 95) / 96, 64), 256, SM2>>>(B2, WT3, b3, B3, 2044, 2044, 1020);
    k4<<<dim3((508 + 95) / 96, 64), 256, SM2>>>(B3, WT4, b4, B4, 1020, 1020, 508);
    // conv5 reads relu(avgpool(B4)): logical Tin=254, raw=508
    k5<<<dim3((125 + 63) / 64, 64), 256, SM5>>>(B4, WT5, b5, B5, 254, 508, 125);
    // conv6 reads relu(avgpool(B5)): logical Tin=62, raw=125
    k6<<<dim3(1, 64), 256, SM6>>>(B5, WT6, b6, B6, 62, 125, 29);
    k7<<<dim3(1, 64), 256, SM7>>>(B6, WT7, b7, B7, 29, 29, 14);

    // Masked max + MLP head
    head_kernel<<<64, 128>>>(B7, lenm, lw1, lb1, lw2, lb2, lw3, lb3,
                             (float*)d_out);
}

// round 3
// speedup vs baseline: 2.0583x; 1.0535x over previous
#include <cuda_runtime.h>
#include <cstdint>
#include <cstddef>

typedef unsigned long long u64;

// ---------------------------------------------------------------------------
// Scratch (single __device__ array; no allocations anywhere)
// ---------------------------------------------------------------------------
static constexpr size_t S_B1  = 64ull * 96 * 4092;
static constexpr size_t S_B2  = 64ull * 96 * 2044;
static constexpr size_t S_B3  = 64ull * 96 * 1020;
static constexpr size_t S_B4  = 64ull * 96 * 508;
static constexpr size_t S_B5  = 64ull * 96 * 125;
static constexpr size_t S_B6  = 64ull * 96 * 29;
static constexpr size_t S_B7  = 64ull * 128 * 14;
static constexpr size_t S_WT1 = 40ull * 10 * 96;    // 38400
static constexpr size_t S_WT2 = 96ull * 5 * 96;     // 46080 (wt2..wt6)
static constexpr size_t S_WT7 = 96ull * 3 * 128;    // 36864

static constexpr size_t OFF_B1  = 0;
static constexpr size_t OFF_B2  = OFF_B1  + S_B1;
static constexpr size_t OFF_B3  = OFF_B2  + S_B2;
static constexpr size_t OFF_B4  = OFF_B3  + S_B3;
static constexpr size_t OFF_B5  = OFF_B4  + S_B4;
static constexpr size_t OFF_B6  = OFF_B5  + S_B5;
static constexpr size_t OFF_B7  = OFF_B6  + S_B6;
static constexpr size_t OFF_WT1 = OFF_B7  + S_B7;
static constexpr size_t OFF_WT2 = OFF_WT1 + S_WT1;
static constexpr size_t OFF_WT3 = OFF_WT2 + S_WT2;
static constexpr size_t OFF_WT4 = OFF_WT3 + S_WT2;
static constexpr size_t OFF_WT5 = OFF_WT4 + S_WT2;
static constexpr size_t OFF_WT6 = OFF_WT5 + S_WT2;
static constexpr size_t OFF_WT7 = OFF_WT6 + S_WT2;
static constexpr size_t SCRATCH_TOTAL = OFF_WT7 + S_WT7;

__device__ float g_scratch[SCRATCH_TOTAL];

// ---------------------------------------------------------------------------
// f32x2 packed-FMA helpers
// ---------------------------------------------------------------------------
__device__ __forceinline__ u64 pk2(float lo, float hi) {
    u64 r;
    asm("mov.b64 %0, {%1, %2};" : "=l"(r)
        : "r"(__float_as_uint(lo)), "r"(__float_as_uint(hi)));
    return r;
}
__device__ __forceinline__ void fma2(u64& d, u64 a, u64 b) {
    asm("fma.rn.f32x2 %0, %1, %2, %0;" : "+l"(d) : "l"(a), "l"(b));
}
__device__ __forceinline__ float2 unpk2(u64 v) {
    unsigned int a, b;
    asm("mov.b64 {%0, %1}, %2;" : "=r"(a), "=r"(b) : "l"(v));
    return make_float2(__uint_as_float(a), __uint_as_float(b));
}

// ---------------------------------------------------------------------------
// Fused weight transpose: w[O][I][K] -> wt[(i*K+k)*O + o], all 7 in one launch
// ---------------------------------------------------------------------------
__device__ __forceinline__ void tp_one(const float* __restrict__ w,
                                       float* __restrict__ wt,
                                       int O, int I, int K, int n) {
    int IK = I * K;
    int o = n / IK;
    int r = n - o * IK;
    int i = r / K;
    int k = r - i * K;
    wt[(i * K + k) * O + o] = w[n];
}

__global__ void transpose_all_kernel(
    const float* __restrict__ w1, const float* __restrict__ w2,
    const float* __restrict__ w3, const float* __restrict__ w4,
    const float* __restrict__ w5, const float* __restrict__ w6,
    const float* __restrict__ w7,
    float* __restrict__ t1, float* __restrict__ t2, float* __restrict__ t3,
    float* __restrict__ t4, float* __restrict__ t5, float* __restrict__ t6,
    float* __restrict__ t7) {
    int n = blockIdx.x * blockDim.x + threadIdx.x;
    if (n < 38400) { tp_one(w1, t1, 96, 40, 10, n); return; }  n -= 38400;
    if (n < 46080) { tp_one(w2, t2, 96, 96, 5, n); return; }   n -= 46080;
    if (n < 46080) { tp_one(w3, t3, 96, 96, 5, n); return; }   n -= 46080;
    if (n < 46080) { tp_one(w4, t4, 96, 96, 5, n); return; }   n -= 46080;
    if (n < 46080) { tp_one(w5, t5, 96, 96, 5, n); return; }   n -= 46080;
    if (n < 46080) { tp_one(w6, t6, 96, 96, 5, n); return; }   n -= 46080;
    if (n < 36864) { tp_one(w7, t7, 128, 96, 3, n); }
}

// ---------------------------------------------------------------------------
// Direct stride-2 VALID conv, fp32 via packed f32x2, CHANNEL-paired.
// Block computes OSUB output channels (O-split via blockIdx.z) over a
// T_TILE time tile for one sample. 256 threads = 32 lanes x 8 groups.
// Optional POOL_IN fuses AvgPool1d(2)+ReLU of the previous layer into the
// smem staging. Input de-interleaved even/odd for conflict-free stride-2.
// ---------------------------------------------------------------------------
template <int I, int O, int OSUB, int K, int ICHUNK, int T_TILE, bool RELU,
          bool POOL_IN>
__global__ __launch_bounds__(256, 2)
void conv_kernel(const float* __restrict__ x, const float* __restrict__ wt,
                 const float* __restrict__ bias, float* __restrict__ y,
                 int Tin, int TinRaw, int Tconv) {
    constexpr int SPAN_H = T_TILE + 8;      // half-span (even/odd arrays)
    constexpr int TO = T_TILE / 32;         // time regs per thread
    constexpr int CO = OSUB / 8;            // channels per thread
    constexpr int CP = CO / 2;              // channel pairs (f32x2)
    constexpr int USPAN = 2 * T_TILE + K + 1;
    static_assert((USPAN + 1) / 2 <= SPAN_H, "span");
    static_assert(OSUB % 16 == 0, "OSUB");

    extern __shared__ float smem[];
    float* xe  = smem;                      // [I][SPAN_H] even phase
    float* xo  = xe + I * SPAN_H;           // [I][SPAN_H] odd phase
    float* wsh = xo + I * SPAN_H;           // [ICHUNK*K][OSUB]

    const int b   = blockIdx.y;
    const int oz  = blockIdx.z;
    const int t0  = blockIdx.x * T_TILE;
    const int tid = threadIdx.x;
    const int tx  = tid & 31;
    const int cy  = tid >> 5;

    // Stage (and optionally pool+relu) input tile
    const float* xb = x + (size_t)b * I * TinRaw;
    for (int n = tid; n < I * USPAN; n += 256) {
        int i = n / USPAN;
        int u = n - i * USPAN;
        int tg = 2 * t0 + u;                // logical input position
        float v = 0.f;
        if (tg < Tin) {
            if (POOL_IN) {
                const float* s = xb + (size_t)i * TinRaw + 2 * tg;
                v = fmaxf(0.5f * (s[0] + s[1]), 0.f);
            } else {
                v = xb[(size_t)i * TinRaw + tg];
            }
        }
        if (u & 1) xo[i * SPAN_H + (u >> 1)] = v;
        else       xe[i * SPAN_H + (u >> 1)] = v;
    }

    // Init accumulators with bias pairs
    u64 acc[CP][TO];
    const u64* bp64 = reinterpret_cast<const u64*>(bias + oz * OSUB) + cy * CP;
#pragma unroll
    for (int p = 0; p < CP; p++) {
        u64 bb = bp64[p];
#pragma unroll
        for (int j = 0; j < TO; j++) acc[p][j] = bb;
    }

    for (int ic0 = 0; ic0 < I; ic0 += ICHUNK) {
        __syncthreads();
        {
            constexpr int C4 = OSUB / 4;
            constexpr int W4 = ICHUNK * K * C4;
            float4* wdst = reinterpret_cast<float4*>(wsh);
            for (int n = tid; n < W4; n += 256) {
                int r = n / C4;
                int c = n - r * C4;
                wdst[n] = *reinterpret_cast<const float4*>(
                    wt + ((size_t)ic0 * K + r) * O + oz * OSUB + c * 4);
            }
        }
        __syncthreads();

        for (int ic = 0; ic < ICHUNK; ic++) {
            const float* xer = xe + (ic0 + ic) * SPAN_H + tx;
            const float* xod = xo + (ic0 + ic) * SPAN_H + tx;
#pragma unroll
            for (int k = 0; k < K; k++) {
                const float* xs = (k & 1) ? xod : xer;
                const int h = k >> 1;
                u64 xp[TO];
#pragma unroll
                for (int j = 0; j < TO; j++) {
                    float xv = xs[h + 32 * j];
                    xp[j] = pk2(xv, xv);
                }
                const u64* w64 =
                    reinterpret_cast<const u64*>(wsh + (ic * K + k) * OSUB) +
                    cy * CP;
#pragma unroll
                for (int p = 0; p < CP; p++) {
                    u64 wp = w64[p];        // (w[o], w[o+1]) packed, LDS.64
#pragma unroll
                    for (int j = 0; j < TO; j++) fma2(acc[p][j], wp, xp[j]);
                }
            }
        }
    }

    // Store: lanes write consecutive t per channel row (coalesced)
#pragma unroll
    for (int p = 0; p < CP; p++) {
        const int o0 = oz * OSUB + cy * CO + 2 * p;
        float* y0 = y + ((size_t)b * O + o0) * Tconv;
        float* y1 = y0 + Tconv;
#pragma unroll
        for (int j = 0; j < TO; j++) {
            float2 v = unpk2(acc[p][j]);
            if (RELU) { v.x = fmaxf(v.x, 0.f); v.y = fmaxf(v.y, 0.f); }
            int t = t0 + tx + 32 * j;
            if (t < Tconv) { y0[t] = v.x; y1[t] = v.y; }
        }
    }
}

// ---------------------------------------------------------------------------
// Masked adaptive-max over valid frames + 3-layer MLP head
// ---------------------------------------------------------------------------
__global__ void head_kernel(const float* __restrict__ y7,       // [64][128][14]
                            const int* __restrict__ len_mask,
                            const float* __restrict__ lw1, const float* __restrict__ lb1,
                            const float* __restrict__ lw2, const float* __restrict__ lb2,
                            const float* __restrict__ lw3, const float* __restrict__ lb3,
                            float* __restrict__ out) {
    __shared__ float v[128], h1[128], h2[64];
    const int b = blockIdx.x;
    const int tid = threadIdx.x;

    int L = len_mask[b];
    L = (L - 10) / 2 + 1;   // conv1
    L = (L - 5) / 2 + 1;    // conv2
    L = (L - 5) / 2 + 1;    // conv3
    L = (L - 5) / 2 + 1;    // conv4
    L >>= 1;                // pool
    L = (L - 5) / 2 + 1;    // conv5
    L >>= 1;                // pool
    L = (L - 5) / 2 + 1;    // conv6
    L = (L - 3) / 2 + 1;    // conv7
    if (L > 14) L = 14;
    if (L < 1)  L = 1;

    const float* row = y7 + ((size_t)b * 128 + tid) * 14;
    float m = -3.4e38f;
    for (int t = 0; t < L; t++) m = fmaxf(m, row[t]);
    v[tid] = m;
    __syncthreads();

    float s = lb1[tid];
#pragma unroll 8
    for (int i = 0; i < 128; i++) s += lw1[tid * 128 + i] * v[i];
    h1[tid] = fmaxf(s, 0.f);
    __syncthreads();

    if (tid < 64) {
        float s2 = lb2[tid];
#pragma unroll 8
        for (int i = 0; i < 128; i++) s2 += lw2[tid * 128 + i] * h1[i];
        h2[tid] = fmaxf(s2, 0.f);
    }
    __syncthreads();

    if (tid < 5) {
        float s3 = lb3[tid];
#pragma unroll 8
        for (int i = 0; i < 64; i++) s3 += lw3[tid * 64 + i] * h2[i];
        out[b * 5 + tid] = s3;
    }
}

// ---------------------------------------------------------------------------
// Launch
// ---------------------------------------------------------------------------
extern "C" void kernel_launch(void* const* d_in, const int* in_sizes, int n_in,
                              void* d_out, int out_size) {
    const float* x    = (const float*)d_in[0];
    const int*   lenm = (const int*)d_in[1];
    const float* w1 = (const float*)d_in[2];  const float* b1 = (const float*)d_in[3];
    const float* w2 = (const float*)d_in[4];  const float* b2 = (const float*)d_in[5];
    const float* w3 = (const float*)d_in[6];  const float* b3 = (const float*)d_in[7];
    const float* w4 = (const float*)d_in[8];  const float* b4 = (const float*)d_in[9];
    const float* w5 = (const float*)d_in[10]; const float* b5 = (const float*)d_in[11];
    const float* w6 = (const float*)d_in[12]; const float* b6 = (const float*)d_in[13];
    const float* w7 = (const float*)d_in[14]; const float* b7 = (const float*)d_in[15];
    const float* lw1 = (const float*)d_in[16]; const float* lb1 = (const float*)d_in[17];
    const float* lw2 = (const float*)d_in[18]; const float* lb2 = (const float*)d_in[19];
    const float* lw3 = (const float*)d_in[20]; const float* lb3 = (const float*)d_in[21];

    float* base = nullptr;
    cudaGetSymbolAddress((void**)&base, g_scratch);
    float* B1  = base + OFF_B1;
    float* B2  = base + OFF_B2;
    float* B3  = base + OFF_B3;
    float* B4  = base + OFF_B4;
    float* B5  = base + OFF_B5;
    float* B6  = base + OFF_B6;
    float* B7  = base + OFF_B7;
    float* WT1 = base + OFF_WT1;
    float* WT2 = base + OFF_WT2;
    float* WT3 = base + OFF_WT3;
    float* WT4 = base + OFF_WT4;
    float* WT5 = base + OFF_WT5;
    float* WT6 = base + OFF_WT6;
    float* WT7 = base + OFF_WT7;

    // Instantiations:        I   O  OSUB  K  IC  T   RELU  POOL
    auto k1 = conv_kernel<40, 96, 96, 10, 10, 160, true,  false>;
    auto k2 = conv_kernel<96, 96, 96,  5,  4, 128, true,  false>;
    auto k4 = conv_kernel<96, 96, 96,  5,  4, 128, false, false>;
    auto k5 = conv_kernel<96, 96, 48,  5, 16,  64, false, true>;
    auto k6 = conv_kernel<96, 96, 48,  5, 16,  32, true,  true>;
    auto k7 = conv_kernel<96, 128, 64, 3, 32,  32, true,  false>;

    // dynamic smem bytes
    const int SM1 = (2 * 40 * 168 + 10 * 10 * 96) * 4;   // 92160
    const int SM2 = (2 * 96 * 136 + 4 * 5 * 96) * 4;     // 112128
    const int SM5 = (2 * 96 * 72  + 16 * 5 * 48) * 4;    // 70656
    const int SM6 = (2 * 96 * 40  + 16 * 5 * 48) * 4;    // 46080
    const int SM7 = (2 * 96 * 40  + 32 * 3 * 64) * 4;    // 55296

    cudaFuncSetAttribute(k1, cudaFuncAttributeMaxDynamicSharedMemorySize, SM1);
    cudaFuncSetAttribute(k2, cudaFuncAttributeMaxDynamicSharedMemorySize, SM2);
    cudaFuncSetAttribute(k4, cudaFuncAttributeMaxDynamicSharedMemorySize, SM2);
    cudaFuncSetAttribute(k5, cudaFuncAttributeMaxDynamicSharedMemorySize, SM5);
    cudaFuncSetAttribute(k6, cudaFuncAttributeMaxDynamicSharedMemorySize, SM6);
    cudaFuncSetAttribute(k7, cudaFuncAttributeMaxDynamicSharedMemorySize, SM7);

    // 0: all weight transposes fused
    transpose_all_kernel<<<(38400 + 5 * 46080 + 36864 + 255) / 256, 256>>>(
        w1, w2, w3, w4, w5, w6, w7, WT1, WT2, WT3, WT4, WT5, WT6, WT7);

    // 1: conv1 — single launch, 26x64 = 1664 blocks (5.6 waves, eff ~0.94)
    k1<<<dim3(26, 64, 1), 256, SM1>>>(x, WT1, b1, B1, 8192, 8192, 4092);
    // 2: conv2 — 16x64 = 1024 blocks
    k2<<<dim3(16, 64, 1), 256, SM2>>>(B1, WT2, b2, B2, 4092, 4092, 2044);
    // 3: conv3 — 8x64 = 512 blocks
    k2<<<dim3(8, 64, 1), 256, SM2>>>(B2, WT3, b3, B3, 2044, 2044, 1020);
    // 4: conv4 — 4x64 = 256 blocks (exactly one wave)
    k4<<<dim3(4, 64, 1), 256, SM2>>>(B3, WT4, b4, B4, 1020, 1020, 508);
    // 5: conv5 (pool+relu of B4 fused) — 2x64x2 = 256 blocks
    k5<<<dim3(2, 64, 2), 256, SM5>>>(B4, WT5, b5, B5, 254, 508, 125);
    // 6: conv6 (pool+relu of B5 fused) — 1x64x2 = 128 blocks
    k6<<<dim3(1, 64, 2), 256, SM6>>>(B5, WT6, b6, B6, 62, 125, 29);
    // 7: conv7 — 1x64x2 = 128 blocks
    k7<<<dim3(1, 64, 2), 256, SM7>>>(B6, WT7, b7, B7, 29, 29, 14);

    // 8: masked max + MLP head
    head_kernel<<<64, 128>>>(B7, lenm, lw1, lb1, lw2, lb2, lw3, lb3,
                             (float*)d_out);
}

// round 6
// speedup vs baseline: 2.1170x; 1.0285x over previous
#include <cuda_runtime.h>
#include <cuda_bf16.h>
#include <cstdint>
#include <cstddef>

typedef unsigned long long u64;
typedef unsigned int u32;

// ---------------------------------------------------------------------------
// Scratch (single __device__ array; no allocations anywhere)
// ---------------------------------------------------------------------------
static constexpr size_t S_B1  = 64ull * 96 * 4092;
static constexpr size_t S_B2  = 64ull * 96 * 2044;
static constexpr size_t S_B3  = 64ull * 96 * 1020;
static constexpr size_t S_B4  = 64ull * 96 * 508;
static constexpr size_t S_B5  = 64ull * 96 * 125;
static constexpr size_t S_B6  = 64ull * 96 * 29;
static constexpr size_t S_B7  = 64ull * 128 * 14;
static constexpr size_t S_WT  = 96ull * 5 * 96;     // wt5, wt6
static constexpr size_t S_WT7 = 96ull * 3 * 128;

static constexpr size_t OFF_B1  = 0;
static constexpr size_t OFF_B2  = OFF_B1  + S_B1;
static constexpr size_t OFF_B3  = OFF_B2  + S_B2;
static constexpr size_t OFF_B4  = OFF_B3  + S_B3;
static constexpr size_t OFF_B5  = OFF_B4  + S_B4;
static constexpr size_t OFF_B6  = OFF_B5  + S_B5;
static constexpr size_t OFF_B7  = OFF_B6  + S_B6;
static constexpr size_t OFF_WT5 = OFF_B7  + S_B7;
static constexpr size_t OFF_WT6 = OFF_WT5 + S_WT;
static constexpr size_t OFF_WT7 = OFF_WT6 + S_WT;
static constexpr size_t SCRATCH_TOTAL = OFF_WT7 + S_WT7;

__device__ float g_scratch[SCRATCH_TOTAL];

// ---------------------------------------------------------------------------
// mma.sync / ldmatrix helpers (baseline PTX — compiles at compute_103)
// ---------------------------------------------------------------------------
__device__ __forceinline__ void ldsm_x4(u32* r, u32 addr) {
    asm volatile("ldmatrix.sync.aligned.m8n8.x4.shared.b16 {%0,%1,%2,%3}, [%4];"
                 : "=r"(r[0]), "=r"(r[1]), "=r"(r[2]), "=r"(r[3]) : "r"(addr));
}
__device__ __forceinline__ void ldsm_x2(u32* r, u32 addr) {
    asm volatile("ldmatrix.sync.aligned.m8n8.x2.shared.b16 {%0,%1}, [%2];"
                 : "=r"(r[0]), "=r"(r[1]) : "r"(addr));
}
__device__ __forceinline__ void mma_bf16(float* d, const u32* a, const u32* b) {
    asm volatile(
        "mma.sync.aligned.m16n8k16.row.col.f32.bf16.bf16.f32 "
        "{%0,%1,%2,%3}, {%4,%5,%6,%7}, {%8,%9}, {%0,%1,%2,%3};"
        : "+f"(d[0]), "+f"(d[1]), "+f"(d[2]), "+f"(d[3])
        : "r"(a[0]), "r"(a[1]), "r"(a[2]), "r"(a[3]), "r"(b[0]), "r"(b[1]));
}

// fp32 -> bf16 hi/lo split, two elements packed per u32
__device__ __forceinline__ void split2(float a0, float a1, u32& hi, u32& lo) {
    __nv_bfloat16 h0 = __float2bfloat16_rn(a0);
    __nv_bfloat16 h1 = __float2bfloat16_rn(a1);
    __nv_bfloat16 l0 = __float2bfloat16_rn(a0 - __bfloat162float(h0));
    __nv_bfloat16 l1 = __float2bfloat16_rn(a1 - __bfloat162float(h1));
    hi = (u32)__bfloat16_as_ushort(h0) | ((u32)__bfloat16_as_ushort(h1) << 16);
    lo = (u32)__bfloat16_as_ushort(l0) | ((u32)__bfloat16_as_ushort(l1) << 16);
}

#define STS128(addr, a, b, c, d) \
    asm volatile("st.shared.v4.b32 [%0], {%1, %2, %3, %4};" \
                 :: "r"((u32)(addr)), "r"(a), "r"(b), "r"(c), "r"(d) : "memory")

__device__ __forceinline__ u32 smem_u32(const void* p) {
    u32 a;
    asm("{ .reg .u64 t; cvta.to.shared.u64 t, %1; cvt.u32.u64 %0, t; }"
        : "=r"(a) : "l"(p));
    return a;
}

// smem layout calc (host + device agree); AP = 72 bf16 row pitch (144B)
__host__ __device__ constexpr int hmma_xpitch(int K) { return (256 + K + 7) & ~7; }
__host__ __device__ constexpr int hmma_a_off(int I, int K) {
    return (512 + I * hmma_xpitch(K) * 4 + 15) & ~15;
}
__host__ __device__ constexpr int hmma_smem(int I, int O, int K) {
    int total = hmma_a_off(I, K) + 2 * 128 * 144 + 2 * O * 144;
    int dmin = 512 + 128 * 97 * 4;   // Dtile overlay
    return total > dmin ? total : dmin;
}

// ---------------------------------------------------------------------------
// Implicit-GEMM conv via register MMA (HMMA), bf16 2-term split, 3 passes.
// D[t(128), o(O)] = sum_ik im2col(x)[t,ik] * w[o,ik];  stride-2 VALID conv.
// One CTA per (batch b, 128-wide t tile). 256 threads = 8 warps; warp w owns
// rows [16w,16w+16) x all O cols. Weights read directly in torch layout.
// ---------------------------------------------------------------------------
template <int I, int O, int K, bool RELU>
__global__ __launch_bounds__(256, 1)
void conv_hmma_kernel(const float* __restrict__ x, const float* __restrict__ w,
                      const float* __restrict__ bias, float* __restrict__ y,
                      int Tin, int Tconv) {
    constexpr int IK = I * K;
    constexpr int NCH = (IK + 63) / 64;     // 64-wide k chunks
    constexpr int NT = O / 8;               // n tiles per warp
    constexpr int XP = hmma_xpitch(K);
    constexpr int AP2 = 144;                // bf16 row pitch in bytes (72*2)
    constexpr int A_OFF = hmma_a_off(I, K);
    constexpr int ALO_OFF = A_OFF + 128 * AP2;
    constexpr int BHI_OFF = ALO_OFF + 128 * AP2;
    constexpr int BLO_OFF = BHI_OFF + O * AP2;
    static_assert(IK % 8 == 0, "IK mult of 8");

    extern __shared__ char smem[];
    const u32 sm = smem_u32(smem);
    float* bias_sh = reinterpret_cast<float*>(smem);            // [O]
    float* xraw    = reinterpret_cast<float*>(smem + 512);      // [I][XP]

    const int b    = blockIdx.y;
    const int t0   = blockIdx.x * 128;
    const int tid  = threadIdx.x;
    const int wid  = tid >> 5;
    const int lane = tid & 31;

    if (tid < O) bias_sh[tid] = bias[tid];

    // stage raw input slice: x[b][i][2*t0 + u], u in [0, 256+K)
    const float* xb = x + (size_t)b * I * Tin;
    for (int n = tid; n < I * (256 + K); n += 256) {
        int i = n / (256 + K);
        int u = n - i * (256 + K);
        int tg = 2 * t0 + u;
        xraw[i * XP + u] = (tg < Tin) ? xb[(size_t)i * Tin + tg] : 0.f;
    }

    // per-lane ldmatrix address offsets
    // A (x4): tile0 rows0-7 k0 | tile1 rows8-15 k0 | tile2 rows0-7 k0+8 | tile3 rows8-15 k0+8
    const int a_row = 16 * wid + (lane & 7) + ((lane >> 3) & 1) * 8;
    const u32 a_loff = (u32)(a_row * AP2 + (lane >> 4) * 16);
    // B (x2): lanes0-7 rows n0.. k0 | lanes8-15 rows n0.. k0+8
    const int bl = lane & 15;
    const u32 b_loff = (u32)((bl & 7) * AP2 + (bl >> 3) * 16);

    float acc[NT][4];
#pragma unroll
    for (int nt = 0; nt < NT; nt++)
#pragma unroll
        for (int q = 0; q < 4; q++) acc[nt][q] = 0.f;

    for (int ch = 0; ch < NCH; ch++) {
        __syncthreads();   // prior chunk fully consumed

        // ---- stage A chunk: [128 t][64 ck] bf16 hi/lo -------------------
        {
            const u32 ah = sm + A_OFF, al = sm + ALO_OFF;
#pragma unroll
            for (int unit = tid; unit < 1024; unit += 256) {
                int t = unit >> 3, g = unit & 7;
                int cg0 = ch * 64 + g * 8;
                float v[8];
                if (cg0 < IK) {
#pragma unroll
                    for (int e = 0; e < 8; e++) {
                        int cg = cg0 + e;
                        int i = cg / K;
                        int k = cg - i * K;
                        v[e] = xraw[i * XP + 2 * t + k];
                    }
                } else {
#pragma unroll
                    for (int e = 0; e < 8; e++) v[e] = 0.f;
                }
                u32 ph[4], pl[4];
#pragma unroll
                for (int e2 = 0; e2 < 4; e2++)
                    split2(v[2 * e2], v[2 * e2 + 1], ph[e2], pl[e2]);
                u32 off = (u32)(t * AP2 + g * 16);
                STS128(ah + off, ph[0], ph[1], ph[2], ph[3]);
                STS128(al + off, pl[0], pl[1], pl[2], pl[3]);
            }
        }
        // ---- stage B chunk: [O][64 ck] bf16 hi/lo (torch layout w[o][ik])
        {
            const u32 bh = sm + BHI_OFF, blo = sm + BLO_OFF;
#pragma unroll
            for (int unit = tid; unit < O * 8; unit += 256) {
                int o = unit >> 3, g = unit & 7;
                int cg0 = ch * 64 + g * 8;
                float v[8];
                if (cg0 < IK) {
                    const float4* wr =
                        reinterpret_cast<const float4*>(w + (size_t)o * IK + cg0);
                    float4 q0 = wr[0], q1 = wr[1];
                    v[0] = q0.x; v[1] = q0.y; v[2] = q0.z; v[3] = q0.w;
                    v[4] = q1.x; v[5] = q1.y; v[6] = q1.z; v[7] = q1.w;
                } else {
#pragma unroll
                    for (int e = 0; e < 8; e++) v[e] = 0.f;
                }
                u32 ph[4], pl[4];
#pragma unroll
                for (int e2 = 0; e2 < 4; e2++)
                    split2(v[2 * e2], v[2 * e2 + 1], ph[e2], pl[e2]);
                u32 off = (u32)(o * AP2 + g * 16);
                STS128(bh + off, ph[0], ph[1], ph[2], ph[3]);
                STS128(blo + off, pl[0], pl[1], pl[2], pl[3]);
            }
        }
        __syncthreads();

        // ---- compute: 4 k-steps of 16, 3 passes (hh, hl, lh) ------------
        const u32 ah_b = sm + A_OFF + a_loff;
        const u32 al_b = sm + ALO_OFF + a_loff;
        const u32 bh_b = sm + BHI_OFF + b_loff;
        const u32 bl_b = sm + BLO_OFF + b_loff;
#pragma unroll
        for (int ks = 0; ks < 4; ks++) {
            u32 ah[4], al[4];
            ldsm_x4(ah, ah_b + ks * 32);
            ldsm_x4(al, al_b + ks * 32);
#pragma unroll
            for (int nt = 0; nt < NT; nt++) {
                u32 bh[2], blr[2];
                ldsm_x2(bh, bh_b + (u32)(nt * 8 * AP2) + ks * 32);
                ldsm_x2(blr, bl_b + (u32)(nt * 8 * AP2) + ks * 32);
                mma_bf16(acc[nt], ah, bh);   // hi*hi
                mma_bf16(acc[nt], ah, blr);  // hi*lo
                mma_bf16(acc[nt], al, bh);   // lo*hi
            }
        }
    }

    // ---- epilogue: frags -> smem (pitch 97) -> coalesced gmem -----------
    __syncthreads();
    float* Dt = reinterpret_cast<float*>(smem + 512);
    const int g = lane >> 2, c = lane & 3;
    const int r0 = 16 * wid + g;
#pragma unroll
    for (int nt = 0; nt < NT; nt++) {
        int n0 = nt * 8 + 2 * c;
        Dt[r0 * 97 + n0]           = acc[nt][0];
        Dt[r0 * 97 + n0 + 1]       = acc[nt][1];
        Dt[(r0 + 8) * 97 + n0]     = acc[nt][2];
        Dt[(r0 + 8) * 97 + n0 + 1] = acc[nt][3];
    }
    __syncthreads();
    for (int idx = tid; idx < O * 128; idx += 256) {
        int o = idx >> 7, tl = idx & 127;
        int t = t0 + tl;
        if (t < Tconv) {
            float v = Dt[tl * 97 + o] + bias_sh[o];
            if (RELU) v = fmaxf(v, 0.f);
            y[((size_t)b * O + o) * Tconv + t] = v;
        }
    }
}

// ---------------------------------------------------------------------------
// f32x2 helpers + tail conv kernels (conv5-7)
// ---------------------------------------------------------------------------
__device__ __forceinline__ u64 pk2(float lo, float hi) {
    u64 r;
    asm("mov.b64 %0, {%1, %2};" : "=l"(r)
        : "r"(__float_as_uint(lo)), "r"(__float_as_uint(hi)));
    return r;
}
__device__ __forceinline__ void fma2(u64& d, u64 a, u64 b) {
    asm("fma.rn.f32x2 %0, %1, %2, %0;" : "+l"(d) : "l"(a), "l"(b));
}
__device__ __forceinline__ float2 unpk2(u64 v) {
    u32 a, b;
    asm("mov.b64 {%0, %1}, %2;" : "=r"(a), "=r"(b) : "l"(v));
    return make_float2(__uint_as_float(a), __uint_as_float(b));
}

__global__ void transpose_w_kernel(const float* __restrict__ w,
                                   float* __restrict__ wt,
                                   int O, int I, int K) {
    int n = blockIdx.x * blockDim.x + threadIdx.x;
    int total = O * I * K;
    if (n >= total) return;
    int o = n / (I * K);
    int r = n - o * (I * K);
    int i = r / K;
    int k = r - i * K;
    wt[(i * K + k) * O + o] = w[n];
}

template <int I, int O, int OSUB, int K, int ICHUNK, int T_TILE, bool RELU,
          bool POOL_IN>
__global__ __launch_bounds__(256, 2)
void conv_kernel(const float* __restrict__ x, const float* __restrict__ wt,
                 const float* __restrict__ bias, float* __restrict__ y,
                 int Tin, int TinRaw, int Tconv) {
    constexpr int SPAN_H = T_TILE + 8;
    constexpr int TO = T_TILE / 32;
    constexpr int CO = OSUB / 8;
    constexpr int CP = CO / 2;
    constexpr int USPAN = 2 * T_TILE + K + 1;
    static_assert((USPAN + 1) / 2 <= SPAN_H, "span");

    extern __shared__ float fsm[];
    float* xe  = fsm;
    float* xo  = xe + I * SPAN_H;
    float* wsh = xo + I * SPAN_H;

    const int b   = blockIdx.y;
    const int oz  = blockIdx.z;
    const int t0  = blockIdx.x * T_TILE;
    const int tid = threadIdx.x;
    const int tx  = tid & 31;
    const int cy  = tid >> 5;

    const float* xb = x + (size_t)b * I * TinRaw;
    for (int n = tid; n < I * USPAN; n += 256) {
        int i = n / USPAN;
        int u = n - i * USPAN;
        int tg = 2 * t0 + u;
        float v = 0.f;
        if (tg < Tin) {
            if (POOL_IN) {
                const float* s = xb + (size_t)i * TinRaw + 2 * tg;
                v = fmaxf(0.5f * (s[0] + s[1]), 0.f);
            } else {
                v = xb[(size_t)i * TinRaw + tg];
            }
        }
        if (u & 1) xo[i * SPAN_H + (u >> 1)] = v;
        else       xe[i * SPAN_H + (u >> 1)] = v;
    }

    u64 acc[CP][TO];
    const u64* bp64 = reinterpret_cast<const u64*>(bias + oz * OSUB) + cy * CP;
#pragma unroll
    for (int p = 0; p < CP; p++) {
        u64 bb = bp64[p];
#pragma unroll
        for (int j = 0; j < TO; j++) acc[p][j] = bb;
    }

    for (int ic0 = 0; ic0 < I; ic0 += ICHUNK) {
        __syncthreads();
        {
            constexpr int C4 = OSUB / 4;
            constexpr int W4 = ICHUNK * K * C4;
            float4* wdst = reinterpret_cast<float4*>(wsh);
            for (int n = tid; n < W4; n += 256) {
                int r = n / C4;
                int c = n - r * C4;
                wdst[n] = *reinterpret_cast<const float4*>(
                    wt + ((size_t)ic0 * K + r) * O + oz * OSUB + c * 4);
            }
        }
        __syncthreads();

        for (int ic = 0; ic < ICHUNK; ic++) {
            const float* xer = xe + (ic0 + ic) * SPAN_H + tx;
            const float* xod = xo + (ic0 + ic) * SPAN_H + tx;
#pragma unroll
            for (int k = 0; k < K; k++) {
                const float* xs = (k & 1) ? xod : xer;
                const int h = k >> 1;
                u64 xp[TO];
#pragma unroll
                for (int j = 0; j < TO; j++) {
                    float xv = xs[h + 32 * j];
                    xp[j] = pk2(xv, xv);
                }
                const u64* w64 =
                    reinterpret_cast<const u64*>(wsh + (ic * K + k) * OSUB) +
                    cy * CP;
#pragma unroll
                for (int p = 0; p < CP; p++) {
                    u64 wp = w64[p];
#pragma unroll
                    for (int j = 0; j < TO; j++) fma2(acc[p][j], wp, xp[j]);
                }
            }
        }
    }

#pragma unroll
    for (int p = 0; p < CP; p++) {
        const int o0 = oz * OSUB + cy * CO + 2 * p;
        float* y0 = y + ((size_t)b * O + o0) * Tconv;
        float* y1 = y0 + Tconv;
#pragma unroll
        for (int j = 0; j < TO; j++) {
            float2 v = unpk2(acc[p][j]);
            if (RELU) { v.x = fmaxf(v.x, 0.f); v.y = fmaxf(v.y, 0.f); }
            int t = t0 + tx + 32 * j;
            if (t < Tconv) { y0[t] = v.x; y1[t] = v.y; }
        }
    }
}

// ---------------------------------------------------------------------------
// Masked adaptive-max over valid frames + 3-layer MLP head
// ---------------------------------------------------------------------------
__global__ void head_kernel(const float* __restrict__ y7,       // [64][128][14]
                            const int* __restrict__ len_mask,
                            const float* __restrict__ lw1, const float* __restrict__ lb1,
                            const float* __restrict__ lw2, const float* __restrict__ lb2,
                            const float* __restrict__ lw3, const float* __restrict__ lb3,
                            float* __restrict__ out) {
    __shared__ float v[128], h1[128], h2[64];
    const int b = blockIdx.x;
    const int tid = threadIdx.x;

    int L = len_mask[b];
    L = (L - 10) / 2 + 1;
    L = (L - 5) / 2 + 1;
    L = (L - 5) / 2 + 1;
    L = (L - 5) / 2 + 1;
    L >>= 1;
    L = (L - 5) / 2 + 1;
    L >>= 1;
    L = (L - 5) / 2 + 1;
    L = (L - 3) / 2 + 1;
    if (L > 14) L = 14;
    if (L < 1)  L = 1;

    const float* row = y7 + ((size_t)b * 128 + tid) * 14;
    float m = -3.4e38f;
    for (int t = 0; t < L; t++) m = fmaxf(m, row[t]);
    v[tid] = m;
    __syncthreads();

    float s = lb1[tid];
#pragma unroll 8
    for (int i = 0; i < 128; i++) s += lw1[tid * 128 + i] * v[i];
    h1[tid] = fmaxf(s, 0.f);
    __syncthreads();

    if (tid < 64) {
        float s2 = lb2[tid];
#pragma unroll 8
        for (int i = 0; i < 128; i++) s2 += lw2[tid * 128 + i] * h1[i];
        h2[tid] = fmaxf(s2, 0.f);
    }
    __syncthreads();

    if (tid < 5) {
        float s3 = lb3[tid];
#pragma unroll 8
        for (int i = 0; i < 64; i++) s3 += lw3[tid * 64 + i] * h2[i];
        out[b * 5 + tid] = s3;
    }
}

// ---------------------------------------------------------------------------
// Launch
// ---------------------------------------------------------------------------
extern "C" void kernel_launch(void* const* d_in, const int* in_sizes, int n_in,
                              void* d_out, int out_size) {
    const float* x    = (const float*)d_in[0];
    const int*   lenm = (const int*)d_in[1];
    const float* w1 = (const float*)d_in[2];  const float* b1 = (const float*)d_in[3];
    const float* w2 = (const float*)d_in[4];  const float* b2 = (const float*)d_in[5];
    const float* w3 = (const float*)d_in[6];  const float* b3 = (const float*)d_in[7];
    const float* w4 = (const float*)d_in[8];  const float* b4 = (const float*)d_in[9];
    const float* w5 = (const float*)d_in[10]; const float* b5 = (const float*)d_in[11];
    const float* w6 = (const float*)d_in[12]; const float* b6 = (const float*)d_in[13];
    const float* w7 = (const float*)d_in[14]; const float* b7 = (const float*)d_in[15];
    const float* lw1 = (const float*)d_in[16]; const float* lb1 = (const float*)d_in[17];
    const float* lw2 = (const float*)d_in[18]; const float* lb2 = (const float*)d_in[19];
    const float* lw3 = (const float*)d_in[20]; const float* lb3 = (const float*)d_in[21];

    float* base = nullptr;
    cudaGetSymbolAddress((void**)&base, g_scratch);
    float* B1  = base + OFF_B1;
    float* B2  = base + OFF_B2;
    float* B3  = base + OFF_B3;
    float* B4  = base + OFF_B4;
    float* B5  = base + OFF_B5;
    float* B6  = base + OFF_B6;
    float* B7  = base + OFF_B7;
    float* WT5 = base + OFF_WT5;
    float* WT6 = base + OFF_WT6;
    float* WT7 = base + OFF_WT7;

    // tensor-core (register HMMA) conv kernels
    auto m1 = conv_hmma_kernel<40, 96, 10, true>;
    auto m2 = conv_hmma_kernel<96, 96, 5, true>;   // conv2, conv3
    auto m4 = conv_hmma_kernel<96, 96, 5, false>;  // conv4 (relu after pool)
    const int SMM1 = hmma_smem(40, 96, 10);
    const int SMM2 = hmma_smem(96, 96, 5);
    cudaFuncSetAttribute(m1, cudaFuncAttributeMaxDynamicSharedMemorySize, SMM1);
    cudaFuncSetAttribute(m2, cudaFuncAttributeMaxDynamicSharedMemorySize, SMM2);
    cudaFuncSetAttribute(m4, cudaFuncAttributeMaxDynamicSharedMemorySize, SMM2);

    // f32x2 tail kernels
    auto k5 = conv_kernel<96, 96, 48, 5, 16, 64, false, true>;
    auto k6 = conv_kernel<96, 96, 48, 5, 16, 32, true,  true>;
    auto k7 = conv_kernel<96, 128, 64, 3, 32, 32, true, false>;
    const int SM5 = (2 * 96 * 72 + 16 * 5 * 48) * 4;
    const int SM6 = (2 * 96 * 40 + 16 * 5 * 48) * 4;
    const int SM7 = (2 * 96 * 40 + 32 * 3 * 64) * 4;
    cudaFuncSetAttribute(k5, cudaFuncAttributeMaxDynamicSharedMemorySize, SM5);
    cudaFuncSetAttribute(k6, cudaFuncAttributeMaxDynamicSharedMemorySize, SM6);
    cudaFuncSetAttribute(k7, cudaFuncAttributeMaxDynamicSharedMemorySize, SM7);

    // 0-2: weight transposes for the f32x2 tail
    transpose_w_kernel<<<(96 * 96 * 5 + 255) / 256, 256>>>(w5, WT5, 96, 96, 5);
    transpose_w_kernel<<<(96 * 96 * 5 + 255) / 256, 256>>>(w6, WT6, 96, 96, 5);
    transpose_w_kernel<<<(128 * 96 * 3 + 255) / 256, 256>>>(w7, WT7, 128, 96, 3);

    // 3-6: HMMA convs (launch #5 = conv3 for ncu)
    m1<<<dim3(32, 64), 256, SMM1>>>(x,  w1, b1, B1, 8192, 4092);
    m2<<<dim3(16, 64), 256, SMM2>>>(B1, w2, b2, B2, 4092, 2044);
    m2<<<dim3(8, 64),  256, SMM2>>>(B2, w3, b3, B3, 2044, 1020);
    m4<<<dim3(4, 64),  256, SMM2>>>(B3, w4, b4, B4, 1020, 508);

    // 7-9: f32x2 tail (pool+relu fused into staging)
    k5<<<dim3(2, 64, 2), 256, SM5>>>(B4, WT5, b5, B5, 254, 508, 125);
    k6<<<dim3(1, 64, 2), 256, SM6>>>(B5, WT6, b6, B6, 62, 125, 29);
    k7<<<dim3(1, 64, 2), 256, SM7>>>(B6, WT7, b7, B7, 29, 29, 14);

    // 10: masked max + MLP head
    head_kernel<<<64, 128>>>(B7, lenm, lw1, lb1, lw2, lb2, lw3, lb3,
                             (float*)d_out);
}

// round 7
// speedup vs baseline: 3.3935x; 1.6029x over previous
#include <cuda_runtime.h>
#include <cuda_bf16.h>
#include <cstdint>
#include <cstddef>

typedef unsigned long long u64;
typedef unsigned int u32;
typedef unsigned short u16;

// ---------------------------------------------------------------------------
// Scratch (device globals; no allocations anywhere)
// ---------------------------------------------------------------------------
static constexpr size_t S_B1  = 64ull * 96 * 4092;
static constexpr size_t S_B2  = 64ull * 96 * 2044;
static constexpr size_t S_B3  = 64ull * 96 * 1020;
static constexpr size_t S_B4  = 64ull * 96 * 508;
static constexpr size_t S_B5  = 64ull * 96 * 125;
static constexpr size_t S_B6  = 64ull * 96 * 29;
static constexpr size_t S_B7  = 64ull * 128 * 14;
static constexpr size_t S_WT  = 96ull * 5 * 96;
static constexpr size_t S_WT7 = 96ull * 3 * 128;

static constexpr size_t OFF_B1  = 0;
static constexpr size_t OFF_B2  = OFF_B1  + S_B1;
static constexpr size_t OFF_B3  = OFF_B2  + S_B2;
static constexpr size_t OFF_B4  = OFF_B3  + S_B3;
static constexpr size_t OFF_B5  = OFF_B4  + S_B4;
static constexpr size_t OFF_B6  = OFF_B5  + S_B5;
static constexpr size_t OFF_B7  = OFF_B6  + S_B6;
static constexpr size_t OFF_WT5 = OFF_B7  + S_B7;
static constexpr size_t OFF_WT6 = OFF_WT5 + S_WT;
static constexpr size_t OFF_WT7 = OFF_WT6 + S_WT;
static constexpr size_t SCRATCH_TOTAL = OFF_WT7 + S_WT7;

__device__ float g_scratch[SCRATCH_TOTAL];

// pre-split weights (bf16 hi/lo, chunk-padded [NCH][96][64])
static constexpr int W1H = 0,      W1L = 43008;     // NCH=7
static constexpr int W2H = 86016,  W2L = 135168;    // NCH=8
static constexpr int W3H = 184320, W3L = 233472;
static constexpr int W4H = 282624, W4L = 331776;
__device__ __align__(256) u16 g_wsplit[380928];

// ---------------------------------------------------------------------------
// PTX helpers (baseline ISA only — compiles at compute_103)
// ---------------------------------------------------------------------------
__device__ __forceinline__ void ldsm_x4(u32* r, u32 addr) {
    asm volatile("ldmatrix.sync.aligned.m8n8.x4.shared.b16 {%0,%1,%2,%3}, [%4];"
                 : "=r"(r[0]), "=r"(r[1]), "=r"(r[2]), "=r"(r[3]) : "r"(addr));
}
__device__ __forceinline__ void mma_bf16(float* d, const u32* a, const u32* b) {
    asm volatile(
        "mma.sync.aligned.m16n8k16.row.col.f32.bf16.bf16.f32 "
        "{%0,%1,%2,%3}, {%4,%5,%6,%7}, {%8,%9}, {%0,%1,%2,%3};"
        : "+f"(d[0]), "+f"(d[1]), "+f"(d[2]), "+f"(d[3])
        : "r"(a[0]), "r"(a[1]), "r"(a[2]), "r"(a[3]), "r"(b[0]), "r"(b[1]));
}
#define CP_ASYNC16(dst, src) \
    asm volatile("cp.async.cg.shared.global [%0], [%1], 16;" \
                 :: "r"((u32)(dst)), "l"(src) : "memory")
#define CP_ASYNC_COMMIT() asm volatile("cp.async.commit_group;" ::: "memory")
#define CP_ASYNC_WAIT0()  asm volatile("cp.async.wait_group 0;" ::: "memory")
#define STS128(addr, a, b, c, d) \
    asm volatile("st.shared.v4.b32 [%0], {%1, %2, %3, %4};" \
                 :: "r"((u32)(addr)), "r"(a), "r"(b), "r"(c), "r"(d) : "memory")

__device__ __forceinline__ u32 smem_u32(const void* p) {
    u32 a;
    asm("{ .reg .u64 t; cvta.to.shared.u64 t, %1; cvt.u32.u64 %0, t; }"
        : "=r"(a) : "l"(p));
    return a;
}

// fp32 -> packed (bf16 hi | bf16 lo << 16)
__device__ __forceinline__ u32 split1(float v) {
    __nv_bfloat16 h = __float2bfloat16_rn(v);
    __nv_bfloat16 l = __float2bfloat16_rn(v - __bfloat162float(h));
    return (u32)__bfloat16_as_ushort(h) | ((u32)__bfloat16_as_ushort(l) << 16);
}

// smem layout (bytes); M tile = 64, O = 96, pitch 144
__host__ __device__ constexpr int hx_xp(int K) { return (128 + K + 3) & ~3; }
__host__ __device__ constexpr int hx_ahi(int I, int K) {
    return (512 + I * hx_xp(K) * 4 + 15) & ~15;
}
__host__ __device__ constexpr int hx_smem(int I, int K) {
    return hx_ahi(I, K) + 2 * 64 * 144 + 2 * 96 * 144;
}

// ---------------------------------------------------------------------------
// Weight pre-split: w[O][IK] f32 -> [NCH][96][64] bf16 hi/lo (zero-padded)
// ---------------------------------------------------------------------------
__global__ void presplit_w_kernel(const float* __restrict__ w1,
                                  const float* __restrict__ w2,
                                  const float* __restrict__ w3,
                                  const float* __restrict__ w4) {
    int n = blockIdx.x * blockDim.x + threadIdx.x;
    const float* w; int IK; u16 *hi, *lo; int idx;
    if (n < 43008)       { w = w1; IK = 400; hi = g_wsplit + W1H; lo = g_wsplit + W1L; idx = n; }
    else if (n < 92160)  { w = w2; IK = 480; hi = g_wsplit + W2H; lo = g_wsplit + W2L; idx = n - 43008; }
    else if (n < 141312) { w = w3; IK = 480; hi = g_wsplit + W3H; lo = g_wsplit + W3L; idx = n - 92160; }
    else if (n < 190464) { w = w4; IK = 480; hi = g_wsplit + W4H; lo = g_wsplit + W4L; idx = n - 141312; }
    else return;
    int c  = idx & 63;
    int o  = (idx >> 6) % 96;
    int ch = idx / (64 * 96);
    int cg = ch * 64 + c;
    float v = (cg < IK) ? w[o * IK + cg] : 0.f;
    u32 p = split1(v);
    hi[idx] = (u16)(p & 0xFFFF);
    lo[idx] = (u16)(p >> 16);
}

// ---------------------------------------------------------------------------
// Implicit-GEMM conv via HMMA, bf16 split, 3 passes. M tile = 64, O = 96.
// 8 warps = 4 m-warps x 2 n-warps; warp tile m16 x n48. 2 CTAs/SM.
// ---------------------------------------------------------------------------
template <int I, int K, bool RELU>
__global__ __launch_bounds__(256, 2)
void conv_hmma_kernel(const float* __restrict__ x,
                      const u16* __restrict__ whi, const u16* __restrict__ wlo,
                      const float* __restrict__ bias, float* __restrict__ y,
                      int Tin, int Tconv) {
    constexpr int IK = I * K;
    constexpr int NCH = (IK + 63) / 64;
    constexpr int USPAN = 128 + K;
    constexpr int XP = hx_xp(K);
    constexpr int A_HI = hx_ahi(I, K);
    constexpr int A_LO = A_HI + 64 * 144;
    constexpr int B_HI = A_LO + 64 * 144;
    constexpr int B_LO = B_HI + 96 * 144;
    static_assert(IK % 8 == 0, "IK mult of 8");

    extern __shared__ char smem[];
    const u32 sm = smem_u32(smem);
    float* bias_sh = reinterpret_cast<float*>(smem);
    u32*   xsp     = reinterpret_cast<u32*>(smem + 512);

    const int b    = blockIdx.y;
    const int t0   = blockIdx.x * 64;
    const int tid  = threadIdx.x;
    const int wid  = tid >> 5;
    const int lane = tid & 31;
    const int mw   = wid & 3;
    const int nw   = wid >> 2;

    if (tid < 96) bias_sh[tid] = bias[tid];

    // split raw x slice once: xsp[i][u] = packed(hi,lo) of x[b][i][2*t0+u]
    const float* xb = x + (size_t)b * I * Tin;
    for (int n = tid; n < I * USPAN; n += 256) {
        int i = n / USPAN;
        int u = n - i * USPAN;
        int tg = 2 * t0 + u;
        float v = (tg < Tin) ? xb[(size_t)i * Tin + tg] : 0.f;
        xsp[i * XP + u] = split1(v);
    }

    // lane ldsm offsets
    const u32 a_loff = (u32)((16 * mw + (lane & 7) + ((lane >> 3) & 1) * 8) * 144
                             + (lane >> 4) * 16);
    const u32 b_loff = (u32)((nw * 48 + ((lane >> 4) << 3) + (lane & 7)) * 144
                             + ((lane >> 3) & 1) * 16);

    float acc[6][4];
#pragma unroll
    for (int nt = 0; nt < 6; nt++)
#pragma unroll
        for (int q = 0; q < 4; q++) acc[nt][q] = 0.f;

    __syncthreads();   // xsp ready

    for (int ch = 0; ch < NCH; ch++) {
        if (ch) __syncthreads();   // previous compute finished

        // B: cp.async from pre-split gmem (96 rows x 128B, hi + lo)
        {
            const u16* srcH = whi + (size_t)ch * 96 * 64;
            const u16* srcL = wlo + (size_t)ch * 96 * 64;
            for (int s = tid; s < 768; s += 256) {
                int o = s >> 3, seg = s & 7;
                CP_ASYNC16(sm + B_HI + o * 144 + seg * 16, srcH + o * 64 + seg * 8);
                CP_ASYNC16(sm + B_LO + o * 144 + seg * 16, srcL + o * 64 + seg * 8);
            }
            CP_ASYNC_COMMIT();
        }

        // A: im2col gather from xsp (packed), PRMT split into hi/lo tiles
        for (int unit = tid; unit < 512; unit += 256) {
            int t = unit >> 3, g = unit & 7;
            int cg0 = ch * 64 + g * 8;
            u32 ph[4], pl[4];
            if (cg0 < IK) {
                u32 s[8];
#pragma unroll
                for (int e = 0; e < 8; e++) {
                    int cg = cg0 + e;
                    int i = cg / K;
                    int k = cg - i * K;
                    s[e] = xsp[i * XP + 2 * t + k];
                }
#pragma unroll
                for (int e2 = 0; e2 < 4; e2++) {
                    ph[e2] = __byte_perm(s[2 * e2], s[2 * e2 + 1], 0x5410);
                    pl[e2] = __byte_perm(s[2 * e2], s[2 * e2 + 1], 0x7632);
                }
            } else {
#pragma unroll
                for (int e2 = 0; e2 < 4; e2++) { ph[e2] = 0; pl[e2] = 0; }
            }
            u32 off = (u32)(t * 144 + g * 16);
            STS128(sm + A_HI + off, ph[0], ph[1], ph[2], ph[3]);
            STS128(sm + A_LO + off, pl[0], pl[1], pl[2], pl[3]);
        }

        CP_ASYNC_WAIT0();
        __syncthreads();

        // compute: 4 k-steps x (3 n-pairs) x 3 passes
        const u32 ah_b = sm + A_HI + a_loff;
        const u32 al_b = sm + A_LO + a_loff;
        const u32 bh_b = sm + B_HI + b_loff;
        const u32 bl_b = sm + B_LO + b_loff;
#pragma unroll
        for (int ks = 0; ks < 4; ks++) {
            u32 ahi[4], alo[4];
            ldsm_x4(ahi, ah_b + ks * 32);
            ldsm_x4(alo, al_b + ks * 32);
#pragma unroll
            for (int p = 0; p < 3; p++) {
                u32 bhi[4], blo[4];
                ldsm_x4(bhi, bh_b + (u32)(p * 16 * 144) + ks * 32);
                ldsm_x4(blo, bl_b + (u32)(p * 16 * 144) + ks * 32);
                mma_bf16(acc[2 * p],     ahi, bhi);
                mma_bf16(acc[2 * p],     ahi, blo);
                mma_bf16(acc[2 * p],     alo, bhi);
                mma_bf16(acc[2 * p + 1], ahi, bhi + 2);
                mma_bf16(acc[2 * p + 1], ahi, blo + 2);
                mma_bf16(acc[2 * p + 1], alo, bhi + 2);
            }
        }
    }

    // epilogue: frags -> smem (pitch 97) -> coalesced gmem
    __syncthreads();
    float* Dt = reinterpret_cast<float*>(smem + 512);
    const int g = lane >> 2, c = lane & 3;
    const int r0 = 16 * mw + g;
#pragma unroll
    for (int nt = 0; nt < 6; nt++) {
        int n0 = nw * 48 + nt * 8 + 2 * c;
        Dt[r0 * 97 + n0]           = acc[nt][0];
        Dt[r0 * 97 + n0 + 1]       = acc[nt][1];
        Dt[(r0 + 8) * 97 + n0]     = acc[nt][2];
        Dt[(r0 + 8) * 97 + n0 + 1] = acc[nt][3];
    }
    __syncthreads();
    for (int idx = tid; idx < 96 * 64; idx += 256) {
        int o = idx >> 6, tl = idx & 63;
        int t = t0 + tl;
        if (t < Tconv) {
            float v = Dt[tl * 97 + o] + bias_sh[o];
            if (RELU) v = fmaxf(v, 0.f);
            y[((size_t)b * 96 + o) * Tconv + t] = v;
        }
    }
}

// ---------------------------------------------------------------------------
// f32x2 helpers + tail conv kernels (conv5-7)
// ---------------------------------------------------------------------------
__device__ __forceinline__ u64 pk2(float lo, float hi) {
    u64 r;
    asm("mov.b64 %0, {%1, %2};" : "=l"(r)
        : "r"(__float_as_uint(lo)), "r"(__float_as_uint(hi)));
    return r;
}
__device__ __forceinline__ void fma2(u64& d, u64 a, u64 b) {
    asm("fma.rn.f32x2 %0, %1, %2, %0;" : "+l"(d) : "l"(a), "l"(b));
}
__device__ __forceinline__ float2 unpk2(u64 v) {
    u32 a, b;
    asm("mov.b64 {%0, %1}, %2;" : "=r"(a), "=r"(b) : "l"(v));
    return make_float2(__uint_as_float(a), __uint_as_float(b));
}

__global__ void transpose_w_kernel(const float* __restrict__ w,
                                   float* __restrict__ wt,
                                   int O, int I, int K) {
    int n = blockIdx.x * blockDim.x + threadIdx.x;
    int total = O * I * K;
    if (n >= total) return;
    int o = n / (I * K);
    int r = n - o * (I * K);
    int i = r / K;
    int k = r - i * K;
    wt[(i * K + k) * O + o] = w[n];
}

template <int I, int O, int OSUB, int K, int ICHUNK, int T_TILE, bool RELU,
          bool POOL_IN>
__global__ __launch_bounds__(256, 2)
void conv_kernel(const float* __restrict__ x, const float* __restrict__ wt,
                 const float* __restrict__ bias, float* __restrict__ y,
                 int Tin, int TinRaw, int Tconv) {
    constexpr int SPAN_H = T_TILE + 8;
    constexpr int TO = T_TILE / 32;
    constexpr int CO = OSUB / 8;
    constexpr int CP = CO / 2;
    constexpr int USPAN = 2 * T_TILE + K + 1;
    static_assert((USPAN + 1) / 2 <= SPAN_H, "span");

    extern __shared__ float fsm[];
    float* xe  = fsm;
    float* xo  = xe + I * SPAN_H;
    float* wsh = xo + I * SPAN_H;

    const int b   = blockIdx.y;
    const int oz  = blockIdx.z;
    const int t0  = blockIdx.x * T_TILE;
    const int tid = threadIdx.x;
    const int tx  = tid & 31;
    const int cy  = tid >> 5;

    const float* xb = x + (size_t)b * I * TinRaw;
    for (int n = tid; n < I * USPAN; n += 256) {
        int i = n / USPAN;
        int u = n - i * USPAN;
        int tg = 2 * t0 + u;
        float v = 0.f;
        if (tg < Tin) {
            if (POOL_IN) {
                const float* s = xb + (size_t)i * TinRaw + 2 * tg;
                v = fmaxf(0.5f * (s[0] + s[1]), 0.f);
            } else {
                v = xb[(size_t)i * TinRaw + tg];
            }
        }
        if (u & 1) xo[i * SPAN_H + (u >> 1)] = v;
        else       xe[i * SPAN_H + (u >> 1)] = v;
    }

    u64 acc[CP][TO];
    const u64* bp64 = reinterpret_cast<const u64*>(bias + oz * OSUB) + cy * CP;
#pragma unroll
    for (int p = 0; p < CP; p++) {
        u64 bb = bp64[p];
#pragma unroll
        for (int j = 0; j < TO; j++) acc[p][j] = bb;
    }

    for (int ic0 = 0; ic0 < I; ic0 += ICHUNK) {
        __syncthreads();
        {
            constexpr int C4 = OSUB / 4;
            constexpr int W4 = ICHUNK * K * C4;
            float4* wdst = reinterpret_cast<float4*>(wsh);
            for (int n = tid; n < W4; n += 256) {
                int r = n / C4;
                int c = n - r * C4;
                wdst[n] = *reinterpret_cast<const float4*>(
                    wt + ((size_t)ic0 * K + r) * O + oz * OSUB + c * 4);
            }
        }
        __syncthreads();

        for (int ic = 0; ic < ICHUNK; ic++) {
            const float* xer = xe + (ic0 + ic) * SPAN_H + tx;
            const float* xod = xo + (ic0 + ic) * SPAN_H + tx;
#pragma unroll
            for (int k = 0; k < K; k++) {
                const float* xs = (k & 1) ? xod : xer;
                const int h = k >> 1;
                u64 xp[TO];
#pragma unroll
                for (int j = 0; j < TO; j++) {
                    float xv = xs[h + 32 * j];
                    xp[j] = pk2(xv, xv);
                }
                const u64* w64 =
                    reinterpret_cast<const u64*>(wsh + (ic * K + k) * OSUB) +
                    cy * CP;
#pragma unroll
                for (int p = 0; p < CP; p++) {
                    u64 wp = w64[p];
#pragma unroll
                    for (int j = 0; j < TO; j++) fma2(acc[p][j], wp, xp[j]);
                }
            }
        }
    }

#pragma unroll
    for (int p = 0; p < CP; p++) {
        const int o0 = oz * OSUB + cy * CO + 2 * p;
        float* y0 = y + ((size_t)b * O + o0) * Tconv;
        float* y1 = y0 + Tconv;
#pragma unroll
        for (int j = 0; j < TO; j++) {
            float2 v = unpk2(acc[p][j]);
            if (RELU) { v.x = fmaxf(v.x, 0.f); v.y = fmaxf(v.y, 0.f); }
            int t = t0 + tx + 32 * j;
            if (t < Tconv) { y0[t] = v.x; y1[t] = v.y; }
        }
    }
}

// ---------------------------------------------------------------------------
// Masked adaptive-max over valid frames + 3-layer MLP head
// ---------------------------------------------------------------------------
__global__ void head_kernel(const float* __restrict__ y7,       // [64][128][14]
                            const int* __restrict__ len_mask,
                            const float* __restrict__ lw1, const float* __restrict__ lb1,
                            const float* __restrict__ lw2, const float* __restrict__ lb2,
                            const float* __restrict__ lw3, const float* __restrict__ lb3,
                            float* __restrict__ out) {
    __shared__ float v[128], h1[128], h2[64];
    const int b = blockIdx.x;
    const int tid = threadIdx.x;

    int L = len_mask[b];
    L = (L - 10) / 2 + 1;
    L = (L - 5) / 2 + 1;
    L = (L - 5) / 2 + 1;
    L = (L - 5) / 2 + 1;
    L >>= 1;
    L = (L - 5) / 2 + 1;
    L >>= 1;
    L = (L - 5) / 2 + 1;
    L = (L - 3) / 2 + 1;
    if (L > 14) L = 14;
    if (L < 1)  L = 1;

    const float* row = y7 + ((size_t)b * 128 + tid) * 14;
    float m = -3.4e38f;
    for (int t = 0; t < L; t++) m = fmaxf(m, row[t]);
    v[tid] = m;
    __syncthreads();

    float s = lb1[tid];
#pragma unroll 8
    for (int i = 0; i < 128; i++) s += lw1[tid * 128 + i] * v[i];
    h1[tid] = fmaxf(s, 0.f);
    __syncthreads();

    if (tid < 64) {
        float s2 = lb2[tid];
#pragma unroll 8
        for (int i = 0; i < 128; i++) s2 += lw2[tid * 128 + i] * h1[i];
        h2[tid] = fmaxf(s2, 0.f);
    }
    __syncthreads();

    if (tid < 5) {
        float s3 = lb3[tid];
#pragma unroll 8
        for (int i = 0; i < 64; i++) s3 += lw3[tid * 64 + i] * h2[i];
        out[b * 5 + tid] = s3;
    }
}

// ---------------------------------------------------------------------------
// Launch
// ---------------------------------------------------------------------------
extern "C" void kernel_launch(void* const* d_in, const int* in_sizes, int n_in,
                              void* d_out, int out_size) {
    const float* x    = (const float*)d_in[0];
    const int*   lenm = (const int*)d_in[1];
    const float* w1 = (const float*)d_in[2];  const float* b1 = (const float*)d_in[3];
    const float* w2 = (const float*)d_in[4];  const float* b2 = (const float*)d_in[5];
    const float* w3 = (const float*)d_in[6];  const float* b3 = (const float*)d_in[7];
    const float* w4 = (const float*)d_in[8];  const float* b4 = (const float*)d_in[9];
    const float* w5 = (const float*)d_in[10]; const float* b5 = (const float*)d_in[11];
    const float* w6 = (const float*)d_in[12]; const float* b6 = (const float*)d_in[13];
    const float* w7 = (const float*)d_in[14]; const float* b7 = (const float*)d_in[15];
    const float* lw1 = (const float*)d_in[16]; const float* lb1 = (const float*)d_in[17];
    const float* lw2 = (const float*)d_in[18]; const float* lb2 = (const float*)d_in[19];
    const float* lw3 = (const float*)d_in[20]; const float* lb3 = (const float*)d_in[21];

    float* base = nullptr;
    cudaGetSymbolAddress((void**)&base, g_scratch);
    u16* wsp = nullptr;
    cudaGetSymbolAddress((void**)&wsp, g_wsplit);

    float* B1  = base + OFF_B1;
    float* B2  = base + OFF_B2;
    float* B3  = base + OFF_B3;
    float* B4  = base + OFF_B4;
    float* B5  = base + OFF_B5;
    float* B6  = base + OFF_B6;
    float* B7  = base + OFF_B7;
    float* WT5 = base + OFF_WT5;
    float* WT6 = base + OFF_WT6;
    float* WT7 = base + OFF_WT7;

    // HMMA conv kernels (M tile 64, 2 CTAs/SM)
    auto m1 = conv_hmma_kernel<40, 10, true>;
    auto m2 = conv_hmma_kernel<96, 5, true>;    // conv2, conv3
    auto m4 = conv_hmma_kernel<96, 5, false>;   // conv4
    const int SMM1 = hx_smem(40, 10);
    const int SMM2 = hx_smem(96, 5);
    cudaFuncSetAttribute(m1, cudaFuncAttributeMaxDynamicSharedMemorySize, SMM1);
    cudaFuncSetAttribute(m2, cudaFuncAttributeMaxDynamicSharedMemorySize, SMM2);
    cudaFuncSetAttribute(m4, cudaFuncAttributeMaxDynamicSharedMemorySize, SMM2);

    // f32x2 tail kernels
    auto k5 = conv_kernel<96, 96, 48, 5, 16, 64, false, true>;
    auto k6 = conv_kernel<96, 96, 48, 5, 16, 32, true,  true>;
    auto k7 = conv_kernel<96, 128, 64, 3, 32, 32, true, false>;
    const int SM5 = (2 * 96 * 72 + 16 * 5 * 48) * 4;
    const int SM6 = (2 * 96 * 40 + 16 * 5 * 48) * 4;
    const int SM7 = (2 * 96 * 40 + 32 * 3 * 64) * 4;
    cudaFuncSetAttribute(k5, cudaFuncAttributeMaxDynamicSharedMemorySize, SM5);
    cudaFuncSetAttribute(k6, cudaFuncAttributeMaxDynamicSharedMemorySize, SM6);
    cudaFuncSetAttribute(k7, cudaFuncAttributeMaxDynamicSharedMemorySize, SM7);

    // 0: weight pre-split (conv1-4)
    presplit_w_kernel<<<(190464 + 255) / 256, 256>>>(w1, w2, w3, w4);
    // 1-3: transposes for the f32x2 tail
    transpose_w_kernel<<<(96 * 96 * 5 + 255) / 256, 256>>>(w5, WT5, 96, 96, 5);
    transpose_w_kernel<<<(96 * 96 * 5 + 255) / 256, 256>>>(w6, WT6, 96, 96, 5);
    transpose_w_kernel<<<(128 * 96 * 3 + 255) / 256, 256>>>(w7, WT7, 128, 96, 3);

    // 4-7: HMMA convs (launch #5 = conv2 for ncu)
    m1<<<dim3(64, 64), 256, SMM1>>>(x,  wsp + W1H, wsp + W1L, b1, B1, 8192, 4092);
    m2<<<dim3(32, 64), 256, SMM2>>>(B1, wsp + W2H, wsp + W2L, b2, B2, 4092, 2044);
    m2<<<dim3(16, 64), 256, SMM2>>>(B2, wsp + W3H, wsp + W3L, b3, B3, 2044, 1020);
    m4<<<dim3(8, 64),  256, SMM2>>>(B3, wsp + W4H, wsp + W4L, b4, B4, 1020, 508);

    // 8-10: f32x2 tail (pool+relu fused into staging)
    k5<<<dim3(2, 64, 2), 256, SM5>>>(B4, WT5, b5, B5, 254, 508, 125);
    k6<<<dim3(1, 64, 2), 256, SM6>>>(B5, WT6, b6, B6, 62, 125, 29);
    k7<<<dim3(1, 64, 2), 256, SM7>>>(B6, WT7, b7, B7, 29, 29, 14);

    // 11: masked max + MLP head
    head_kernel<<<64, 128>>>(B7, lenm, lw1, lb1, lw2, lb2, lw3, lb3,
                             (float*)d_out);
}

// round 8
// speedup vs baseline: 3.4905x; 1.0286x over previous
#include <cuda_runtime.h>
#include <cuda_bf16.h>
#include <cstdint>
#include <cstddef>

typedef unsigned long long u64;
typedef unsigned int u32;
typedef unsigned short u16;

// ---------------------------------------------------------------------------
// Scratch buffers (device globals; no allocations anywhere).
// B1..B6 hold packed bf16(hi,lo) u32 per element; B7 holds fp32.
// ---------------------------------------------------------------------------
static constexpr size_t S_B1 = 64ull * 96 * 4092;
static constexpr size_t S_B2 = 64ull * 96 * 2044;
static constexpr size_t S_B3 = 64ull * 96 * 1020;
static constexpr size_t S_B4 = 64ull * 96 * 508;
static constexpr size_t S_B5 = 64ull * 96 * 125;
static constexpr size_t S_B6 = 64ull * 96 * 29;
static constexpr size_t S_B7 = 64ull * 128 * 14;

static constexpr size_t OFF_B1 = 0;
static constexpr size_t OFF_B2 = OFF_B1 + S_B1;
static constexpr size_t OFF_B3 = OFF_B2 + S_B2;
static constexpr size_t OFF_B4 = OFF_B3 + S_B3;
static constexpr size_t OFF_B5 = OFF_B4 + S_B4;
static constexpr size_t OFF_B6 = OFF_B5 + S_B5;
static constexpr size_t OFF_B7 = OFF_B6 + S_B6;
static constexpr size_t SCRATCH_TOTAL = OFF_B7 + S_B7;

__device__ u32 g_scratch[SCRATCH_TOTAL];

// pre-split weights (bf16 hi/lo, chunk-padded [NCH][O][64])
static constexpr int W1H = 0,      W1L = 43008;    // O=96  NCH=7
static constexpr int W2H = 86016,  W2L = 135168;   // O=96  NCH=8
static constexpr int W3H = 184320, W3L = 233472;
static constexpr int W4H = 282624, W4L = 331776;
static constexpr int W5H = 380928, W5L = 430080;
static constexpr int W6H = 479232, W6L = 528384;
static constexpr int W7H = 577536, W7L = 618496;   // O=128 NCH=5
__device__ __align__(256) u16 g_wsplit[659456];

// ---------------------------------------------------------------------------
// PTX helpers (baseline ISA only — compiles at compute_103)
// ---------------------------------------------------------------------------
__device__ __forceinline__ void ldsm_x4(u32* r, u32 addr) {
    asm volatile("ldmatrix.sync.aligned.m8n8.x4.shared.b16 {%0,%1,%2,%3}, [%4];"
                 : "=r"(r[0]), "=r"(r[1]), "=r"(r[2]), "=r"(r[3]) : "r"(addr));
}
__device__ __forceinline__ void mma_bf16(float* d, const u32* a, const u32* b) {
    asm volatile(
        "mma.sync.aligned.m16n8k16.row.col.f32.bf16.bf16.f32 "
        "{%0,%1,%2,%3}, {%4,%5,%6,%7}, {%8,%9}, {%0,%1,%2,%3};"
        : "+f"(d[0]), "+f"(d[1]), "+f"(d[2]), "+f"(d[3])
        : "r"(a[0]), "r"(a[1]), "r"(a[2]), "r"(a[3]), "r"(b[0]), "r"(b[1]));
}
#define CP_ASYNC16(dst, src) \
    asm volatile("cp.async.cg.shared.global [%0], [%1], 16;" \
                 :: "r"((u32)(dst)), "l"(src) : "memory")
#define CP_ASYNC_COMMIT() asm volatile("cp.async.commit_group;" ::: "memory")
#define CP_ASYNC_WAIT0()  asm volatile("cp.async.wait_group 0;" ::: "memory")
#define STS128(addr, a, b, c, d) \
    asm volatile("st.shared.v4.b32 [%0], {%1, %2, %3, %4};" \
                 :: "r"((u32)(addr)), "r"(a), "r"(b), "r"(c), "r"(d) : "memory")

__device__ __forceinline__ u32 smem_u32(const void* p) {
    u32 a;
    asm("{ .reg .u64 t; cvta.to.shared.u64 t, %1; cvt.u32.u64 %0, t; }"
        : "=r"(a) : "l"(p));
    return a;
}

// fp32 -> packed (bf16 hi | bf16 lo << 16), value ~= hi + lo
__device__ __forceinline__ u32 split1(float v) {
    __nv_bfloat16 h = __float2bfloat16_rn(v);
    __nv_bfloat16 l = __float2bfloat16_rn(v - __bfloat162float(h));
    return (u32)__bfloat16_as_ushort(h) | ((u32)__bfloat16_as_ushort(l) << 16);
}
// packed -> fp32 (hi + lo)
__device__ __forceinline__ float unsplit1(u32 p) {
    return __bfloat162float(__ushort_as_bfloat16((u16)(p & 0xFFFF))) +
           __bfloat162float(__ushort_as_bfloat16((u16)(p >> 16)));
}

// smem layout (bytes); M tile = 64, row pitch 144B
__host__ __device__ constexpr int hx_xp(int K) { return (128 + K + 3) & ~3; }
__host__ __device__ constexpr int hx_ahi(int I, int K) {
    return (512 + I * hx_xp(K) * 4 + 15) & ~15;
}
__host__ __device__ constexpr int hx_smem(int I, int O, int K) {
    int total = hx_ahi(I, K) + 2 * 64 * 144 + 2 * O * 144;
    int dmin = 512 + 64 * (O + 1) * 4;
    return total > dmin ? total : dmin;
}

// ---------------------------------------------------------------------------
// Weight pre-split: w[O][IK] f32 -> [NCH][O][64] bf16 hi/lo (zero-padded)
// ---------------------------------------------------------------------------
__global__ void presplit_w_kernel(
    const float* __restrict__ w1, const float* __restrict__ w2,
    const float* __restrict__ w3, const float* __restrict__ w4,
    const float* __restrict__ w5, const float* __restrict__ w6,
    const float* __restrict__ w7) {
    int n = blockIdx.x * blockDim.x + threadIdx.x;
    const float* w; int IK, O; u16 *hi, *lo; int idx;
    if      (n < 43008)  { w = w1; IK = 400; O = 96;  hi = g_wsplit + W1H; lo = g_wsplit + W1L; idx = n; }
    else if (n < 92160)  { w = w2; IK = 480; O = 96;  hi = g_wsplit + W2H; lo = g_wsplit + W2L; idx = n - 43008; }
    else if (n < 141312) { w = w3; IK = 480; O = 96;  hi = g_wsplit + W3H; lo = g_wsplit + W3L; idx = n - 92160; }
    else if (n < 190464) { w = w4; IK = 480; O = 96;  hi = g_wsplit + W4H; lo = g_wsplit + W4L; idx = n - 141312; }
    else if (n < 239616) { w = w5; IK = 480; O = 96;  hi = g_wsplit + W5H; lo = g_wsplit + W5L; idx = n - 190464; }
    else if (n < 288768) { w = w6; IK = 480; O = 96;  hi = g_wsplit + W6H; lo = g_wsplit + W6L; idx = n - 239616; }
    else if (n < 329728) { w = w7; IK = 288; O = 128; hi = g_wsplit + W7H; lo = g_wsplit + W7L; idx = n - 288768; }
    else return;
    int c  = idx & 63;
    int o  = (idx >> 6) % O;
    int ch = idx / (64 * O);
    int cg = ch * 64 + c;
    float v = (cg < IK) ? w[o * IK + cg] : 0.f;
    u32 p = split1(v);
    hi[idx] = (u16)(p & 0xFFFF);
    lo[idx] = (u16)(p >> 16);
}

// ---------------------------------------------------------------------------
// Implicit-GEMM conv via HMMA, bf16 split, 3 passes. M tile = 64.
// 8 warps = 4 m-warps x 2 n-warps; warp tile m16 x n(O/2). 2 CTAs/SM.
// IN_MODE: 0 = fp32 input, 1 = packed u32 input, 2 = packed + avgpool2 + relu
// OUT_PACKED: store split1(result) as u32 instead of fp32.
// ---------------------------------------------------------------------------
template <int I, int O, int K, bool RELU, int IN_MODE, bool OUT_PACKED>
__global__ __launch_bounds__(256, 2)
void conv_hmma_kernel(const void* __restrict__ xv,
                      const u16* __restrict__ whi, const u16* __restrict__ wlo,
                      const float* __restrict__ bias, void* __restrict__ yv,
                      int Tin, int TinRaw, int Tconv) {
    constexpr int IK = I * K;
    constexpr int NCH = (IK + 63) / 64;
    constexpr int USPAN = 128 + K;
    constexpr int XP = hx_xp(K);
    constexpr int A_HI = hx_ahi(I, K);
    constexpr int A_LO = A_HI + 64 * 144;
    constexpr int B_HI = A_LO + 64 * 144;
    constexpr int B_LO = B_HI + O * 144;
    constexpr int NP = O / 32;           // n-tile pairs per warp
    constexpr int DP = O + 1;            // epilogue smem pitch
    static_assert(IK % 8 == 0, "IK mult of 8");

    extern __shared__ char smem[];
    const u32 sm = smem_u32(smem);
    float* bias_sh = reinterpret_cast<float*>(smem);
    u32*   xsp     = reinterpret_cast<u32*>(smem + 512);

    const int b    = blockIdx.y;
    const int t0   = blockIdx.x * 64;
    const int tid  = threadIdx.x;
    const int wid  = tid >> 5;
    const int lane = tid & 31;
    const int mw   = wid & 3;
    const int nw   = wid >> 2;

    if (tid < O) bias_sh[tid] = bias[tid];

    // stage input slice once as packed (hi,lo) u32s
    for (int n = tid; n < I * USPAN; n += 256) {
        int i = n / USPAN;
        int u = n - i * USPAN;
        int tg = 2 * t0 + u;
        u32 pv = 0;
        if (tg < Tin) {
            if (IN_MODE == 0) {
                const float* xf = (const float*)xv;
                pv = split1(xf[((size_t)b * I + i) * Tin + tg]);
            } else if (IN_MODE == 1) {
                const u32* xu = (const u32*)xv;
                pv = xu[((size_t)b * I + i) * Tin + tg];
            } else {
                const u32* xu = (const u32*)xv;
                const u32* row = xu + ((size_t)b * I + i) * TinRaw + 2 * tg;
                float f = 0.5f * (unsplit1(row[0]) + unsplit1(row[1]));
                pv = split1(fmaxf(f, 0.f));
            }
        }
        xsp[i * XP + u] = pv;
    }

    // ldsm lane offsets
    const u32 a_loff = (u32)((16 * mw + (lane & 7) + ((lane >> 3) & 1) * 8) * 144
                             + (lane >> 4) * 16);
    const u32 b_loff = (u32)((nw * (O / 2) + ((lane >> 4) << 3) + (lane & 7)) * 144
                             + ((lane >> 3) & 1) * 16);

    float acc[2 * NP][4];
#pragma unroll
    for (int nt = 0; nt < 2 * NP; nt++)
#pragma unroll
        for (int q = 0; q < 4; q++) acc[nt][q] = 0.f;

    __syncthreads();   // xsp ready

    for (int ch = 0; ch < NCH; ch++) {
        if (ch) __syncthreads();   // previous compute finished

        // B: cp.async from pre-split gmem (O rows x 128B, hi + lo)
        {
            const u16* srcH = whi + (size_t)ch * O * 64;
            const u16* srcL = wlo + (size_t)ch * O * 64;
            for (int s = tid; s < O * 8; s += 256) {
                int o = s >> 3, seg = s & 7;
                CP_ASYNC16(sm + B_HI + o * 144 + seg * 16, srcH + o * 64 + seg * 8);
                CP_ASYNC16(sm + B_LO + o * 144 + seg * 16, srcL + o * 64 + seg * 8);
            }
            CP_ASYNC_COMMIT();
        }

        // A: im2col gather from xsp (packed), PRMT split into hi/lo tiles
        for (int unit = tid; unit < 512; unit += 256) {
            int t = unit >> 3, g = unit & 7;
            int cg0 = ch * 64 + g * 8;
            u32 ph[4], pl[4];
            if (cg0 < IK) {
                u32 s[8];
#pragma unroll
                for (int e = 0; e < 8; e++) {
                    int cg = cg0 + e;
                    int i = cg / K;
                    int k = cg - i * K;
                    s[e] = xsp[i * XP + 2 * t + k];
                }
#pragma unroll
                for (int e2 = 0; e2 < 4; e2++) {
                    ph[e2] = __byte_perm(s[2 * e2], s[2 * e2 + 1], 0x5410);
                    pl[e2] = __byte_perm(s[2 * e2], s[2 * e2 + 1], 0x7632);
                }
            } else {
#pragma unroll
                for (int e2 = 0; e2 < 4; e2++) { ph[e2] = 0; pl[e2] = 0; }
            }
            u32 off = (u32)(t * 144 + g * 16);
            STS128(sm + A_HI + off, ph[0], ph[1], ph[2], ph[3]);
            STS128(sm + A_LO + off, pl[0], pl[1], pl[2], pl[3]);
        }

        CP_ASYNC_WAIT0();
        __syncthreads();

        // compute: 4 k-steps x NP n-pairs x 3 passes (hh, hl, lh)
        const u32 ah_b = sm + A_HI + a_loff;
        const u32 al_b = sm + A_LO + a_loff;
        const u32 bh_b = sm + B_HI + b_loff;
        const u32 bl_b = sm + B_LO + b_loff;
#pragma unroll
        for (int ks = 0; ks < 4; ks++) {
            u32 ahi[4], alo[4];
            ldsm_x4(ahi, ah_b + ks * 32);
            ldsm_x4(alo, al_b + ks * 32);
#pragma unroll
            for (int p = 0; p < NP; p++) {
                u32 bhi[4], blo[4];
                ldsm_x4(bhi, bh_b + (u32)(p * 16 * 144) + ks * 32);
                ldsm_x4(blo, bl_b + (u32)(p * 16 * 144) + ks * 32);
                mma_bf16(acc[2 * p],     ahi, bhi);
                mma_bf16(acc[2 * p],     ahi, blo);
                mma_bf16(acc[2 * p],     alo, bhi);
                mma_bf16(acc[2 * p + 1], ahi, bhi + 2);
                mma_bf16(acc[2 * p + 1], ahi, blo + 2);
                mma_bf16(acc[2 * p + 1], alo, bhi + 2);
            }
        }
    }

    // epilogue: frags -> smem (pitch DP) -> coalesced gmem
    __syncthreads();
    float* Dt = reinterpret_cast<float*>(smem + 512);
    const int g = lane >> 2, c = lane & 3;
    const int r0 = 16 * mw + g;
#pragma unroll
    for (int nt = 0; nt < 2 * NP; nt++) {
        int n0 = nw * (O / 2) + nt * 8 + 2 * c;
        Dt[r0 * DP + n0]           = acc[nt][0];
        Dt[r0 * DP + n0 + 1]       = acc[nt][1];
        Dt[(r0 + 8) * DP + n0]     = acc[nt][2];
        Dt[(r0 + 8) * DP + n0 + 1] = acc[nt][3];
    }
    __syncthreads();
    for (int idx = tid; idx < O * 64; idx += 256) {
        int o = idx >> 6, tl = idx & 63;
        int t = t0 + tl;
        if (t < Tconv) {
            float v = Dt[tl * DP + o] + bias_sh[o];
            if (RELU) v = fmaxf(v, 0.f);
            size_t oi = ((size_t)b * O + o) * Tconv + t;
            if (OUT_PACKED) ((u32*)yv)[oi] = split1(v);
            else            ((float*)yv)[oi] = v;
        }
    }
}

// ---------------------------------------------------------------------------
// Masked adaptive-max over valid frames + 3-layer MLP head
// ---------------------------------------------------------------------------
__global__ void head_kernel(const float* __restrict__ y7,       // [64][128][14]
                            const int* __restrict__ len_mask,
                            const float* __restrict__ lw1, const float* __restrict__ lb1,
                            const float* __restrict__ lw2, const float* __restrict__ lb2,
                            const float* __restrict__ lw3, const float* __restrict__ lb3,
                            float* __restrict__ out) {
    __shared__ float v[128], h1[128], h2[64];
    const int b = blockIdx.x;
    const int tid = threadIdx.x;

    int L = len_mask[b];
    L = (L - 10) / 2 + 1;
    L = (L - 5) / 2 + 1;
    L = (L - 5) / 2 + 1;
    L = (L - 5) / 2 + 1;
    L >>= 1;
    L = (L - 5) / 2 + 1;
    L >>= 1;
    L = (L - 5) / 2 + 1;
    L = (L - 3) / 2 + 1;
    if (L > 14) L = 14;
    if (L < 1)  L = 1;

    const float* row = y7 + ((size_t)b * 128 + tid) * 14;
    float m = -3.4e38f;
    for (int t = 0; t < L; t++) m = fmaxf(m, row[t]);
    v[tid] = m;
    __syncthreads();

    float s = lb1[tid];
#pragma unroll 8
    for (int i = 0; i < 128; i++) s += lw1[tid * 128 + i] * v[i];
    h1[tid] = fmaxf(s, 0.f);
    __syncthreads();

    if (tid < 64) {
        float s2 = lb2[tid];
#pragma unroll 8
        for (int i = 0; i < 128; i++) s2 += lw2[tid * 128 + i] * h1[i];
        h2[tid] = fmaxf(s2, 0.f);
    }
    __syncthreads();

    if (tid < 5) {
        float s3 = lb3[tid];
#pragma unroll 8
        for (int i = 0; i < 64; i++) s3 += lw3[tid * 64 + i] * h2[i];
        out[b * 5 + tid] = s3;
    }
}

// ---------------------------------------------------------------------------
// Launch
// ---------------------------------------------------------------------------
extern "C" void kernel_launch(void* const* d_in, const int* in_sizes, int n_in,
                              void* d_out, int out_size) {
    const float* x    = (const float*)d_in[0];
    const int*   lenm = (const int*)d_in[1];
    const float* w1 = (const float*)d_in[2];  const float* b1 = (const float*)d_in[3];
    const float* w2 = (const float*)d_in[4];  const float* b2 = (const float*)d_in[5];
    const float* w3 = (const float*)d_in[6];  const float* b3 = (const float*)d_in[7];
    const float* w4 = (const float*)d_in[8];  const float* b4 = (const float*)d_in[9];
    const float* w5 = (const float*)d_in[10]; const float* b5 = (const float*)d_in[11];
    const float* w6 = (const float*)d_in[12]; const float* b6 = (const float*)d_in[13];
    const float* w7 = (const float*)d_in[14]; const float* b7 = (const float*)d_in[15];
    const float* lw1 = (const float*)d_in[16]; const float* lb1 = (const float*)d_in[17];
    const float* lw2 = (const float*)d_in[18]; const float* lb2 = (const float*)d_in[19];
    const float* lw3 = (const float*)d_in[20]; const float* lb3 = (const float*)d_in[21];

    u32* base = nullptr;
    cudaGetSymbolAddress((void**)&base, g_scratch);
    u16* wsp = nullptr;
    cudaGetSymbolAddress((void**)&wsp, g_wsplit);

    u32* B1 = base + OFF_B1;
    u32* B2 = base + OFF_B2;
    u32* B3 = base + OFF_B3;
    u32* B4 = base + OFF_B4;
    u32* B5 = base + OFF_B5;
    u32* B6 = base + OFF_B6;
    float* B7 = (float*)(base + OFF_B7);

    // kernels:                I   O    K  RELU  IN  OUTPK
    auto m1 = conv_hmma_kernel<40, 96, 10, true,  0, true>;
    auto m2 = conv_hmma_kernel<96, 96,  5, true,  1, true>;   // conv2, conv3
    auto m4 = conv_hmma_kernel<96, 96,  5, false, 1, true>;   // conv4
    auto m5 = conv_hmma_kernel<96, 96,  5, false, 2, true>;   // conv5 (pool+relu in)
    auto m6 = conv_hmma_kernel<96, 96,  5, true,  2, true>;   // conv6 (pool+relu in)
    auto m7 = conv_hmma_kernel<96, 128, 3, true,  1, false>;  // conv7 -> fp32

    const int SM1 = hx_smem(40, 96, 10);
    const int SM2 = hx_smem(96, 96, 5);
    const int SM7 = hx_smem(96, 128, 3);
    cudaFuncSetAttribute(m1, cudaFuncAttributeMaxDynamicSharedMemorySize, SM1);
    cudaFuncSetAttribute(m2, cudaFuncAttributeMaxDynamicSharedMemorySize, SM2);
    cudaFuncSetAttribute(m4, cudaFuncAttributeMaxDynamicSharedMemorySize, SM2);
    cudaFuncSetAttribute(m5, cudaFuncAttributeMaxDynamicSharedMemorySize, SM2);
    cudaFuncSetAttribute(m6, cudaFuncAttributeMaxDynamicSharedMemorySize, SM2);
    cudaFuncSetAttribute(m7, cudaFuncAttributeMaxDynamicSharedMemorySize, SM7);

    // 0: weight pre-split (all 7 conv weights)
    presplit_w_kernel<<<(329728 + 255) / 256, 256>>>(w1, w2, w3, w4, w5, w6, w7);

    // 1-7: HMMA convs
    m1<<<dim3(64, 64), 256, SM1>>>(x,  wsp + W1H, wsp + W1L, b1, B1, 8192, 8192, 4092);
    m2<<<dim3(32, 64), 256, SM2>>>(B1, wsp + W2H, wsp + W2L, b2, B2, 4092, 4092, 2044);
    m2<<<dim3(16, 64), 256, SM2>>>(B2, wsp + W3H, wsp + W3L, b3, B3, 2044, 2044, 1020);
    m4<<<dim3(8, 64),  256, SM2>>>(B3, wsp + W4H, wsp + W4L, b4, B4, 1020, 1020, 508);
    m5<<<dim3(2, 64),  256, SM2>>>(B4, wsp + W5H, wsp + W5L, b5, B5, 254, 508, 125);
    m6<<<dim3(1, 64),  256, SM2>>>(B5, wsp + W6H, wsp + W6L, b6, B6, 62, 125, 29);
    m7<<<dim3(1, 64),  256, SM7>>>(B6, wsp + W7H, wsp + W7L, b7, B7, 29, 29, 14);

    // 8: masked max + MLP head
    head_kernel<<<64, 128>>>(B7, lenm, lw1, lb1, lw2, lb2, lw3, lb3,
                             (float*)d_out);
}